// round 2
// baseline (speedup 1.0000x reference)
#include <cuda_runtime.h>
#include <math.h>

// Problem dims (fixed)
#define Bz   2
#define Sq   2048
#define Dm   2048
#define Hh   16
#define DHd  128
#define DFFd 8192
#define ROWS (Bz*Sq)       // 4096
#define BHn  (Bz*Hh)       // 32
#define KLP  144           // 129 padded to mult of 16
#define EPSn 1e-6f

// ---------------- scratch (device globals; no allocation allowed) ----------------
__device__ float g_u   [(size_t)ROWS*Dm];      // residual stream in tangent space
__device__ float g_v   [(size_t)ROWS*Dm];      // normed tangent (v1 then v2)
__device__ float g_q   [(size_t)ROWS*Dm];
__device__ float g_k   [(size_t)ROWS*Dm];
__device__ float g_vv  [(size_t)ROWS*Dm];
__device__ float g_qlm [(size_t)BHn*Sq*KLP];   // metric+scale folded lorentz q
__device__ float g_kl  [(size_t)BHn*Sq*KLP];   // lorentz k
__device__ float g_probs[(size_t)BHn*Sq*Sq];   // scores -> probs (512MB)
__device__ float g_attn[(size_t)ROWS*Dm];      // attention output (B,S,H*DH)
__device__ float g_ffn [(size_t)ROWS*DFFd];    // gelu(v@W1)

// ---------------- reductions ----------------
__device__ __forceinline__ float warpSum(float v){
    #pragma unroll
    for (int o=16;o;o>>=1) v += __shfl_xor_sync(0xffffffffu, v, o);
    return v;
}
__device__ __forceinline__ float warpMax(float v){
    #pragma unroll
    for (int o=16;o;o>>=1) v = fmaxf(v, __shfl_xor_sync(0xffffffffu, v, o));
    return v;
}
__device__ __forceinline__ float blockSum(float v){
    __shared__ float sh[32];
    int lane = threadIdx.x & 31, w = threadIdx.x >> 5, nw = (blockDim.x + 31) >> 5;
    v = warpSum(v);
    __syncthreads();
    if (lane == 0) sh[w] = v;
    __syncthreads();
    float r = (lane < nw) ? sh[lane] : 0.f;
    return warpSum(r);
}
__device__ __forceinline__ float blockMax(float v){
    __shared__ float sh[32];
    int lane = threadIdx.x & 31, w = threadIdx.x >> 5, nw = (blockDim.x + 31) >> 5;
    v = warpMax(v);
    __syncthreads();
    if (lane == 0) sh[w] = v;
    __syncthreads();
    float r = (lane < nw) ? sh[lane] : -1e30f;
    return warpMax(r);
}

// ---------------- stage kernels ----------------
// u0 = log_map(x), v1 = scale1 * u0 / rms(u0). 256 thr/row.
__global__ void k_lognorm1(const float* __restrict__ x, const float* __restrict__ scale,
                           float* __restrict__ u, float* __restrict__ v){
    int row = blockIdx.x, tid = threadIdx.x;
    const float* xr = x + (size_t)row*(Dm+1) + 1;
    float loc[8]; float s = 0.f;
    #pragma unroll
    for (int j=0;j<8;j++){ float t = xr[tid + j*256]; loc[j]=t; s += t*t; }
    float n2 = blockSum(s);
    float a  = sqrtf(n2);                                   // sqrt(-K_amb)=1
    float f  = (a < 1e-6f) ? (1.f - a*a*(1.f/6.f)) : (asinhf(a)/fmaxf(a,1e-12f));
    float rms = sqrtf(f*f*n2*(1.f/(float)Dm) + EPSn);
    float inv = 1.f/rms;
    #pragma unroll
    for (int j=0;j<8;j++){
        int d = tid + j*256;
        float ud = f*loc[j];
        u[(size_t)row*Dm + d] = ud;
        v[(size_t)row*Dm + d] = scale[d]*ud*inv;
    }
}

// v2 = scale2 * u / rms(u)
__global__ void k_norm2(const float* __restrict__ u, const float* __restrict__ scale,
                        float* __restrict__ v){
    int row = blockIdx.x, tid = threadIdx.x;
    const float* ur = u + (size_t)row*Dm;
    float loc[8]; float s = 0.f;
    #pragma unroll
    for (int j=0;j<8;j++){ float t = ur[tid + j*256]; loc[j]=t; s += t*t; }
    float n2 = blockSum(s);
    float rms = sqrtf(n2*(1.f/(float)Dm) + EPSn);
    float inv = 1.f/rms;
    #pragma unroll
    for (int j=0;j<8;j++){
        int d = tid + j*256;
        v[(size_t)row*Dm + d] = scale[d]*loc[j]*inv;
    }
}

// Per-head exp_map for q,k -> 129-dim lorentz vectors, metric+2/sqrt(DH) folded into q.
__global__ void k_qlkl(const float* __restrict__ headK,
                       const float* __restrict__ qsrc, const float* __restrict__ ksrc,
                       float* __restrict__ qlm, float* __restrict__ kl){
    int bs = blockIdx.x;            // b*Sq + s
    int h  = blockIdx.y;
    int which = blockIdx.z;         // 0 -> q, 1 -> k
    int tid = threadIdx.x;          // 128
    const float* src = (which==0) ? qsrc : ksrc;
    float val = src[(size_t)bs*Dm + h*DHd + tid];
    float n2 = blockSum(val*val);
    float Kh = headK[h];
    float a  = sqrtf(-Kh)*sqrtf(n2);
    float sinc = (a < 1e-6f) ? (1.f + a*a*(1.f/6.f)) : (sinhf(a)/fmaxf(a,1e-12f));
    float xi = sinc*val;
    float x0 = sqrtf(-1.f/Kh + sinc*sinc*n2);
    int b = bs / Sq, s = bs % Sq;
    float* dst = ((which==0)? qlm : kl) + ((size_t)(b*Hh + h)*Sq + s)*KLP;
    if (which==0){
        const float gsc = 0.1767766952966369f;   // 2/sqrt(128)
        dst[1+tid] = gsc*xi;
        if (tid==0) dst[0] = -gsc*x0;
    } else {
        dst[1+tid] = xi;
        if (tid==0) dst[0] = x0;
    }
    if (tid < KLP-1-DHd) dst[1+DHd+tid] = 0.f;   // zero pad 129..143
}

// Causal softmax over probs rows, zero-fills k>q.
__global__ void k_softmax(float* __restrict__ probs){
    int row = blockIdx.x;               // bh*Sq + q
    int q = row % Sq;
    float* p = probs + (size_t)row*Sq;
    int tid = threadIdx.x;              // 256
    float e[8]; float m = -1e30f;
    #pragma unroll
    for (int j=0;j<8;j++){
        int k = tid + j*256;
        float sv = (k <= q) ? p[k] : -1e30f;
        e[j] = sv; m = fmaxf(m, sv);
    }
    m = blockMax(m);
    float s = 0.f;
    #pragma unroll
    for (int j=0;j<8;j++){
        float ex = (e[j] > -1e29f) ? expf(e[j]-m) : 0.f;
        e[j] = ex; s += ex;
    }
    s = blockSum(s);
    float inv = 1.f/s;
    #pragma unroll
    for (int j=0;j<8;j++) p[tid + j*256] = e[j]*inv;
}

// Final exp_map to output (B,S,2049)
__global__ void k_expmap(const float* __restrict__ u, float* __restrict__ out){
    int row = blockIdx.x, tid = threadIdx.x;
    const float* ur = u + (size_t)row*Dm;
    float loc[8]; float s = 0.f;
    #pragma unroll
    for (int j=0;j<8;j++){ float t = ur[tid + j*256]; loc[j]=t; s += t*t; }
    float n2 = blockSum(s);
    float a = sqrtf(n2);
    float sinc = (a < 1e-6f) ? (1.f + a*a*(1.f/6.f)) : (sinhf(a)/fmaxf(a,1e-12f));
    float x0 = sqrtf(1.f + sinc*sinc*n2);
    float* o = out + (size_t)row*(Dm+1);
    if (tid==0) o[0] = x0;
    #pragma unroll
    for (int j=0;j<8;j++){ int d = tid + j*256; o[1+d] = sinc*loc[j]; }
}

// ---------------- generic tiled SGEMM ----------------
// C[M,N] = A[M,K] @ op(B), NT=1 -> B is [N,K] row-major (B^T used).
// EPI: 0 none, 1 exact gelu, 2 add ADD (same layout/ld as C).
// CSKIP: skip tiles with n0 > m0 (causal score tiles).
// CKLIM: limit K loop to m0+128 (causal PV).
// bmode/cmode: 0 -> batch offset bz*stride; 1 -> per-(b,h) head slice of (B,S,H*DH).
#define BM 128
#define BN 128
#define BKt 16

template<int EPI, int NT, int CSKIP, int CKLIM>
__global__ void __launch_bounds__(256)
k_gemm(const float* __restrict__ Ag, const float* __restrict__ Bg,
       float* __restrict__ Cg, const float* __restrict__ ADDg,
       int M, int N, int K, int lda, int ldb, int ldc,
       long long sA, long long sB, long long sC,
       int bmode, int cmode){
    int n0 = blockIdx.x*BN, m0 = blockIdx.y*BM, bz = blockIdx.z;
    if (CSKIP && n0 > m0) return;

    long long offA = (long long)bz * sA;
    long long offB = bmode ? ((long long)(bz>>4)*(long long)Sq*Dm + (long long)(bz&15)*DHd)
                           : (long long)bz * sB;
    long long offC = cmode ? ((long long)(bz>>4)*(long long)Sq*Dm + (long long)(bz&15)*DHd)
                           : (long long)bz * sC;
    const float* A = Ag + offA;
    const float* B = Bg + offB;
    float*       C = Cg + offC;
    const float* ADD = ADDg ? (ADDg + offC) : nullptr;

    int kEnd = K;
    if (CKLIM) kEnd = min(K, m0 + BM);

    __shared__ float As[BKt][BM+1];
    __shared__ float Bs[BKt][BN+4];

    int tid = threadIdx.x;
    int ty = tid >> 4, tx = tid & 15;
    float acc[8][8];
    #pragma unroll
    for (int i=0;i<8;i++)
        #pragma unroll
        for (int j=0;j<8;j++) acc[i][j] = 0.f;

    for (int k0 = 0; k0 < kEnd; k0 += BKt){
        // A tile: 128 rows x 16 k -> transposed into As
        #pragma unroll
        for (int r=0;r<2;r++){
            int vv4 = tid + r*256;
            int row = vv4 >> 2, c4 = (vv4 & 3)*4;
            float4 a4 = *(const float4*)&A[(long long)(m0+row)*lda + k0 + c4];
            As[c4+0][row]=a4.x; As[c4+1][row]=a4.y; As[c4+2][row]=a4.z; As[c4+3][row]=a4.w;
        }
        if (!NT){
            // B tile: 16 k-rows x 128 n
            #pragma unroll
            for (int r=0;r<2;r++){
                int vv4 = tid + r*256;
                int row = vv4 >> 5, c4 = (vv4 & 31)*4;
                float4 b4 = *(const float4*)&B[(long long)(k0+row)*ldb + n0 + c4];
                *(float4*)&Bs[row][c4] = b4;
            }
        } else {
            // B tile from row-major [N,K]: 128 n-rows x 16 k, transposed in
            #pragma unroll
            for (int r=0;r<2;r++){
                int vv4 = tid + r*256;
                int row = vv4 >> 2, c4 = (vv4 & 3)*4;
                float4 b4 = *(const float4*)&B[(long long)(n0+row)*ldb + k0 + c4];
                Bs[c4+0][row]=b4.x; Bs[c4+1][row]=b4.y; Bs[c4+2][row]=b4.z; Bs[c4+3][row]=b4.w;
            }
        }
        __syncthreads();
        #pragma unroll
        for (int kk=0; kk<BKt; kk++){
            float ra[8], rb[8];
            #pragma unroll
            for (int i=0;i<8;i++) ra[i] = As[kk][ty*8+i];
            #pragma unroll
            for (int j=0;j<8;j++) rb[j] = Bs[kk][tx*8+j];
            #pragma unroll
            for (int i=0;i<8;i++)
                #pragma unroll
                for (int j=0;j<8;j++)
                    acc[i][j] = fmaf(ra[i], rb[j], acc[i][j]);
        }
        __syncthreads();
    }

    #pragma unroll
    for (int i=0;i<8;i++){
        int row = m0 + ty*8 + i;
        float* crow = C + (long long)row*ldc + n0 + tx*8;
        const float* arow = ADD ? (ADD + (long long)row*ldc + n0 + tx*8) : nullptr;
        #pragma unroll
        for (int jj=0;jj<2;jj++){
            float vals[4];
            #pragma unroll
            for (int t=0;t<4;t++){
                float val = acc[i][jj*4+t];
                if (EPI==1) val = 0.5f*val*(1.f + erff(val*0.7071067811865475f));
                if (EPI==2) val += arow[jj*4+t];
                vals[t] = val;
            }
            *(float4*)&crow[jj*4] = make_float4(vals[0], vals[1], vals[2], vals[3]);
        }
    }
}

// ---------------- launch ----------------
extern "C" void kernel_launch(void* const* d_in, const int* in_sizes, int n_in,
                              void* d_out, int out_size){
    const float* x      = (const float*)d_in[0];
    // d_in[1]: mask (bool) — known causal, unused
    const float* scale1 = (const float*)d_in[2];
    const float* scale2 = (const float*)d_in[3];
    const float* Wq     = (const float*)d_in[4];
    const float* Wk     = (const float*)d_in[5];
    const float* Wv     = (const float*)d_in[6];
    const float* Wo     = (const float*)d_in[7];
    const float* headK  = (const float*)d_in[8];
    const float* W1     = (const float*)d_in[9];
    const float* W2     = (const float*)d_in[10];
    float* out = (float*)d_out;

    float *u,*v,*q,*k,*vv,*qlm,*kl,*probs,*attn,*ffn;
    cudaGetSymbolAddress((void**)&u,    g_u);
    cudaGetSymbolAddress((void**)&v,    g_v);
    cudaGetSymbolAddress((void**)&q,    g_q);
    cudaGetSymbolAddress((void**)&k,    g_k);
    cudaGetSymbolAddress((void**)&vv,   g_vv);
    cudaGetSymbolAddress((void**)&qlm,  g_qlm);
    cudaGetSymbolAddress((void**)&kl,   g_kl);
    cudaGetSymbolAddress((void**)&probs,g_probs);
    cudaGetSymbolAddress((void**)&attn, g_attn);
    cudaGetSymbolAddress((void**)&ffn,  g_ffn);

    // 1) u0 = log(x); v1 = norm1(u0)
    k_lognorm1<<<ROWS,256>>>(x, scale1, u, v);

    // 2) QKV projections
    dim3 gQ(Dm/BN, ROWS/BM);
    k_gemm<0,0,0,0><<<gQ,256>>>(v, Wq, q,  nullptr, ROWS,Dm,Dm, Dm,Dm,Dm, 0,0,0, 0,0);
    k_gemm<0,0,0,0><<<gQ,256>>>(v, Wk, k,  nullptr, ROWS,Dm,Dm, Dm,Dm,Dm, 0,0,0, 0,0);
    k_gemm<0,0,0,0><<<gQ,256>>>(v, Wv, vv, nullptr, ROWS,Dm,Dm, Dm,Dm,Dm, 0,0,0, 0,0);

    // 3) per-head lorentz lift (metric & scale folded into q)
    k_qlkl<<<dim3(ROWS,Hh,2),128>>>(headK, q, k, qlm, kl);

    // 4) causal scores: probs[bh] = qlm[bh] @ kl[bh]^T   (skip fully-masked tiles)
    dim3 gS(Sq/BN, Sq/BM, BHn);
    k_gemm<0,1,1,0><<<gS,256>>>(qlm, kl, probs, nullptr,
                                Sq,Sq,KLP, KLP,KLP,Sq,
                                (long long)Sq*KLP,(long long)Sq*KLP,(long long)Sq*Sq, 0,0);

    // 5) causal softmax (zero-fills k>q)
    k_softmax<<<BHn*Sq,256>>>(probs);

    // 6) PV: attn[b,s,h*DH+:] = probs[bh] @ Vhead   (k-loop causally limited)
    dim3 gP(1, Sq/BM, BHn);
    k_gemm<0,0,0,1><<<gP,256>>>(probs, vv, attn, nullptr,
                                Sq,DHd,Sq, Sq,Dm,Dm,
                                (long long)Sq*Sq,0,0, 1,1);

    // 7) Wo projection + residual: u1 = u0 + attn@Wo (in place)
    k_gemm<2,0,0,0><<<gQ,256>>>(attn, Wo, u, u, ROWS,Dm,Dm, Dm,Dm,Dm, 0,0,0, 0,0);

    // 8) v2 = norm2(u1)
    k_norm2<<<ROWS,256>>>(u, scale2, v);

    // 9) FFN up + exact gelu
    dim3 gF(DFFd/BN, ROWS/BM);
    k_gemm<1,0,0,0><<<gF,256>>>(v, W1, ffn, nullptr, ROWS,DFFd,Dm, Dm,DFFd,DFFd, 0,0,0, 0,0);

    // 10) FFN down + residual: u2 = u1 + gelu@W2 (in place)
    k_gemm<2,0,0,0><<<gQ,256>>>(ffn, W2, u, u, ROWS,Dm,DFFd, DFFd,Dm,Dm, 0,0,0, 0,0);

    // 11) out = exp_map(u2)
    k_expmap<<<ROWS,256>>>(u, out);
}

// round 4
// speedup vs baseline: 3.1454x; 3.1454x over previous
#include <cuda_runtime.h>
#include <cuda_bf16.h>
#include <math.h>
#include <stdint.h>

// Problem dims (fixed)
#define Bz   2
#define Sq   2048
#define Dm   2048
#define Hh   16
#define DHd  128
#define DFFd 8192
#define ROWS (Bz*Sq)       // 4096
#define BHn  (Bz*Hh)       // 32
#define KLQ  192           // 129 padded to 3*64 for k-chunking
#define EPSn 1e-6f

// ================= PTX helpers (baseline compute_103 features only) =================
__device__ __forceinline__ uint32_t smem_u32(const void* p){
    uint32_t r;
    asm("{ .reg .u64 t; cvta.to.shared.u64 t, %1; cvt.u32.u64 %0, t; }" : "=r"(r) : "l"(p));
    return r;
}
#define MB_INIT(addr,cnt) asm volatile("mbarrier.init.shared.b64 [%0], %1;"::"r"(addr),"r"(cnt):"memory")
#define MB_EXPECT_TX(addr,tx) asm volatile("mbarrier.arrive.expect_tx.shared.b64 _, [%0], %1;"::"r"(addr),"r"(tx):"memory")
#define MB_WAIT(addr, ph) do { \
    asm volatile("{\n\t.reg .pred P1;\n\tWL%=:\n\t" \
        "mbarrier.try_wait.parity.acquire.cta.shared::cta.b64 P1, [%0], %1, 0x989680;\n\t" \
        "@P1 bra.uni WD%=;\n\tbra.uni WL%=;\n\tWD%=:\n\t}" \
        :: "r"(addr), "r"(ph) : "memory"); } while(0)
#define BULK16K(dst, src, mb) asm volatile( \
    "cp.async.bulk.shared::cta.global.mbarrier::complete_tx::bytes [%0], [%1], %2, [%3];" \
    :: "r"(dst), "l"(src), "r"(16384), "r"(mb) : "memory")
#define LDSM4(r0,r1,r2,r3,addr) asm volatile( \
    "ldmatrix.sync.aligned.m8n8.x4.shared.b16 {%0,%1,%2,%3},[%4];" \
    : "=r"(r0),"=r"(r1),"=r"(r2),"=r"(r3) : "r"(addr))
#define MMA16816(c, a, b0, b1) asm volatile( \
    "mma.sync.aligned.m16n8k16.row.col.f32.bf16.bf16.f32 " \
    "{%0,%1,%2,%3},{%4,%5,%6,%7},{%8,%9},{%0,%1,%2,%3};" \
    : "+f"((c)[0]),"+f"((c)[1]),"+f"((c)[2]),"+f"((c)[3]) \
    : "r"((a)[0]),"r"((a)[1]),"r"((a)[2]),"r"((a)[3]), "r"(b0),"r"(b1))
#define SWZ(o) ((o) ^ (((o)>>3)&0x70))

// ================= scratch (device globals) =================
__device__ float g_u   [(size_t)ROWS*Dm];
__device__ float g_v   [(size_t)ROWS*Dm];
__device__ float g_q   [(size_t)ROWS*Dm];
__device__ float g_k   [(size_t)ROWS*Dm];
__device__ float g_vv  [(size_t)ROWS*Dm];
__device__ float g_qlm [(size_t)BHn*Sq*KLQ];
__device__ float g_kl  [(size_t)BHn*Sq*KLQ];
__device__ float g_probs[(size_t)BHn*Sq*Sq];    // 512MB
__device__ float g_attn[(size_t)ROWS*Dm];
__device__ float g_ffn [(size_t)ROWS*DFFd];

// bf16 hi/lo tiled-swizzled (TS) operands, uint4 granules (= elems/8).
// TS: [R,C] as tiles 128r x 64c bf16; tile (tr,kc) at granule (tr*(C/64)+kc)*1024,
// interior: granule index = SWZ(r*128 + g*16)>>4  (g = col/8).
__device__ uint4 g_vh  [(size_t)ROWS*Dm/8],   g_vl  [(size_t)ROWS*Dm/8];
__device__ uint4 g_ath [(size_t)ROWS*Dm/8],   g_atl [(size_t)ROWS*Dm/8];
__device__ uint4 g_fh  [(size_t)ROWS*DFFd/8], g_fl  [(size_t)ROWS*DFFd/8];
__device__ uint4 g_qh  [(size_t)BHn*Sq*KLQ/8], g_ql [(size_t)BHn*Sq*KLQ/8];
__device__ uint4 g_kh  [(size_t)BHn*Sq*KLQ/8], g_klo[(size_t)BHn*Sq*KLQ/8];
__device__ uint4 g_ph  [(size_t)BHn*Sq*Sq/8],  g_pl [(size_t)BHn*Sq*Sq/8];   // 256MB ea
__device__ uint4 g_vth [(size_t)BHn*DHd*Sq/8], g_vtl[(size_t)BHn*DHd*Sq/8];
__device__ uint4 g_WqTh[(size_t)Dm*Dm/8], g_WqTl[(size_t)Dm*Dm/8];
__device__ uint4 g_WkTh[(size_t)Dm*Dm/8], g_WkTl[(size_t)Dm*Dm/8];
__device__ uint4 g_WvTh[(size_t)Dm*Dm/8], g_WvTl[(size_t)Dm*Dm/8];
__device__ uint4 g_WoTh[(size_t)Dm*Dm/8], g_WoTl[(size_t)Dm*Dm/8];
__device__ uint4 g_W1Th[(size_t)Dm*DFFd/8], g_W1Tl[(size_t)Dm*DFFd/8];
__device__ uint4 g_W2Th[(size_t)Dm*DFFd/8], g_W2Tl[(size_t)Dm*DFFd/8];

// ================= reductions =================
__device__ __forceinline__ float warpSum(float v){
    #pragma unroll
    for (int o=16;o;o>>=1) v += __shfl_xor_sync(0xffffffffu, v, o);
    return v;
}
__device__ __forceinline__ float warpMax(float v){
    #pragma unroll
    for (int o=16;o;o>>=1) v = fmaxf(v, __shfl_xor_sync(0xffffffffu, v, o));
    return v;
}
__device__ __forceinline__ float blockSum(float v){
    __shared__ float sh[32];
    int lane = threadIdx.x & 31, w = threadIdx.x >> 5, nw = (blockDim.x + 31) >> 5;
    v = warpSum(v);
    __syncthreads();
    if (lane == 0) sh[w] = v;
    __syncthreads();
    float r = (lane < nw) ? sh[lane] : 0.f;
    return warpSum(r);
}
__device__ __forceinline__ float blockMax(float v){
    __shared__ float sh[32];
    int lane = threadIdx.x & 31, w = threadIdx.x >> 5, nw = (blockDim.x + 31) >> 5;
    v = warpMax(v);
    __syncthreads();
    if (lane == 0) sh[w] = v;
    __syncthreads();
    float r = (lane < nw) ? sh[lane] : -1e30f;
    return warpMax(r);
}

// ================= elementwise stage kernels =================
__global__ void k_lognorm1(const float* __restrict__ x, const float* __restrict__ scale,
                           float* __restrict__ u, float* __restrict__ v){
    int row = blockIdx.x, tid = threadIdx.x;
    const float* xr = x + (size_t)row*(Dm+1) + 1;
    float loc[8]; float s = 0.f;
    #pragma unroll
    for (int j=0;j<8;j++){ float t = xr[tid + j*256]; loc[j]=t; s += t*t; }
    float n2 = blockSum(s);
    float a  = sqrtf(n2);
    float f  = (a < 1e-6f) ? (1.f - a*a*(1.f/6.f)) : (asinhf(a)/fmaxf(a,1e-12f));
    float rms = sqrtf(f*f*n2*(1.f/(float)Dm) + EPSn);
    float inv = 1.f/rms;
    #pragma unroll
    for (int j=0;j<8;j++){
        int d = tid + j*256;
        float ud = f*loc[j];
        u[(size_t)row*Dm + d] = ud;
        v[(size_t)row*Dm + d] = scale[d]*ud*inv;
    }
}
__global__ void k_norm2(const float* __restrict__ u, const float* __restrict__ scale,
                        float* __restrict__ v){
    int row = blockIdx.x, tid = threadIdx.x;
    const float* ur = u + (size_t)row*Dm;
    float loc[8]; float s = 0.f;
    #pragma unroll
    for (int j=0;j<8;j++){ float t = ur[tid + j*256]; loc[j]=t; s += t*t; }
    float n2 = blockSum(s);
    float rms = sqrtf(n2*(1.f/(float)Dm) + EPSn);
    float inv = 1.f/rms;
    #pragma unroll
    for (int j=0;j<8;j++){
        int d = tid + j*256;
        v[(size_t)row*Dm + d] = scale[d]*loc[j]*inv;
    }
}
// q,k -> lorentz (192-padded rows, metric+2/sqrt(DH) folded into q)
__global__ void k_qlkl(const float* __restrict__ headK,
                       const float* __restrict__ qsrc, const float* __restrict__ ksrc,
                       float* __restrict__ qlm, float* __restrict__ kl){
    int bs = blockIdx.x;
    int h  = blockIdx.y;
    int which = blockIdx.z;
    int tid = threadIdx.x;          // 128
    const float* src = (which==0) ? qsrc : ksrc;
    float val = src[(size_t)bs*Dm + h*DHd + tid];
    float n2 = blockSum(val*val);
    float Kh = headK[h];
    float a  = sqrtf(-Kh)*sqrtf(n2);
    float sinc = (a < 1e-6f) ? (1.f + a*a*(1.f/6.f)) : (sinhf(a)/fmaxf(a,1e-12f));
    float xi = sinc*val;
    float x0 = sqrtf(-1.f/Kh + sinc*sinc*n2);
    int b = bs / Sq, s = bs % Sq;
    float* dst = ((which==0)? qlm : kl) + ((size_t)(b*Hh + h)*Sq + s)*KLQ;
    if (which==0){
        const float gsc = 0.1767766952966369f;   // 2/sqrt(128)
        dst[1+tid] = gsc*xi;
        if (tid==0) dst[0] = -gsc*x0;
    } else {
        dst[1+tid] = xi;
        if (tid==0) dst[0] = x0;
    }
    if (tid < 63) dst[129+tid] = 0.f;    // zero pad 129..191
}
__global__ void k_softmax(float* __restrict__ probs){
    int row = blockIdx.x;
    int q = row % Sq;
    float* p = probs + (size_t)row*Sq;
    int tid = threadIdx.x;
    float e[8]; float m = -1e30f;
    #pragma unroll
    for (int j=0;j<8;j++){
        int k = tid + j*256;
        float sv = (k <= q) ? p[k] : -1e30f;
        e[j] = sv; m = fmaxf(m, sv);
    }
    m = blockMax(m);
    float s = 0.f;
    #pragma unroll
    for (int j=0;j<8;j++){
        float ex = (e[j] > -1e29f) ? expf(e[j]-m) : 0.f;
        e[j] = ex; s += ex;
    }
    s = blockSum(s);
    float inv = 1.f/s;
    #pragma unroll
    for (int j=0;j<8;j++) p[tid + j*256] = e[j]*inv;
}
__global__ void k_expmap(const float* __restrict__ u, float* __restrict__ out){
    int row = blockIdx.x, tid = threadIdx.x;
    const float* ur = u + (size_t)row*Dm;
    float loc[8]; float s = 0.f;
    #pragma unroll
    for (int j=0;j<8;j++){ float t = ur[tid + j*256]; loc[j]=t; s += t*t; }
    float n2 = blockSum(s);
    float a = sqrtf(n2);
    float sinc = (a < 1e-6f) ? (1.f + a*a*(1.f/6.f)) : (sinhf(a)/fmaxf(a,1e-12f));
    float x0 = sqrtf(1.f + sinc*sinc*n2);
    float* o = out + (size_t)row*(Dm+1);
    if (tid==0) o[0] = x0;
    #pragma unroll
    for (int j=0;j<8;j++){ int d = tid + j*256; o[1+d] = sinc*loc[j]; }
}

// ================= bf16 hi/lo split kernels -> TS gmem =================
union Pack8 { __nv_bfloat16 b[8]; uint4 v; };

// activations [R,C] -> TS (no transpose). grid (R/128, C/64), 256 thr.
// causal: for probs only (16 tile-rows per bh): skip tiles entirely above diagonal.
__global__ void k_split_act(const float* __restrict__ A, uint4* __restrict__ Hi,
                            uint4* __restrict__ Lo, int C, int causal){
    int tr = blockIdx.x, kc = blockIdx.y; int ntc = C >> 6;
    if (causal && (kc >> 1) > (tr & 15)) return;
    size_t blk = ((size_t)tr*ntc + kc)*1024;
    #pragma unroll
    for (int i=0;i<4;i++){
        int gid = threadIdx.x + i*256;
        int row = gid >> 3, g = gid & 7;
        const float* src = A + ((size_t)(tr*128+row))*C + kc*64 + g*8;
        float4 a = *(const float4*)src;
        float4 b = *(const float4*)(src+4);
        float xs[8] = {a.x,a.y,a.z,a.w,b.x,b.y,b.z,b.w};
        Pack8 uh, ul;
        #pragma unroll
        for (int j=0;j<8;j++){
            __nv_bfloat16 h = __float2bfloat16(xs[j]);
            uh.b[j] = h;
            ul.b[j] = __float2bfloat16(xs[j] - __bfloat162float(h));
        }
        uint32_t off = SWZ((uint32_t)(row*128 + g*16)) >> 4;
        Hi[blk + off] = uh.v;
        Lo[blk + off] = ul.v;
    }
}

// W[K,N] (row stride ld) -> WT[N,K] TS. grid (N/128, K/64, nz), 256 thr.
// hmode: per-(b,h) slice of (B*S, H*DH); outzG = out granules per z.
__global__ void k_split_wT(const float* __restrict__ W, uint4* __restrict__ Hi,
                           uint4* __restrict__ Lo, int K, int N, int ld,
                           int hmode, long long outzG){
    __shared__ float s[64][129];
    int tr = blockIdx.x, kc = blockIdx.y, bz = blockIdx.z;
    int ntc = K >> 6;
    const float* Wb = W + (hmode ? ((long long)(bz>>4)*(long long)Sq*Dm + (long long)(bz&15)*DHd) : 0);
    Hi += (size_t)bz*outzG; Lo += (size_t)bz*outzG;
    int n0 = tr*128, k0 = kc*64;
    int col = threadIdx.x & 127, r0 = threadIdx.x >> 7;
    #pragma unroll
    for (int i=0;i<32;i++){
        int r = r0 + i*2;
        s[r][col] = Wb[(size_t)(k0+r)*ld + n0 + col];
    }
    __syncthreads();
    size_t blk = ((size_t)tr*ntc + kc)*1024;
    #pragma unroll
    for (int i=0;i<4;i++){
        int gid = threadIdx.x + i*256;
        int nl = gid >> 3, g = gid & 7;
        Pack8 uh, ul;
        #pragma unroll
        for (int j=0;j<8;j++){
            float x = s[g*8+j][nl];
            __nv_bfloat16 h = __float2bfloat16(x);
            uh.b[j] = h;
            ul.b[j] = __float2bfloat16(x - __bfloat162float(h));
        }
        uint32_t off = SWZ((uint32_t)(nl*128 + g*16)) >> 4;
        Hi[blk + off] = uh.v;
        Lo[blk + off] = ul.v;
    }
}

// ================= HMMA bf16x3 pipelined GEMM =================
// C[128x128 tile] = A @ B^T, A TS [M,K], B TS [N,K]; hi/lo 3-pass (ah*bh + ah*bl + al*bh).
// 3-stage cp.async.bulk ring, 64KB/stage (Ah,Al,Bh,Bl 16KB blocks).
// EPI: 0 none, 1 exact gelu, 2 += ADD.  CSKIP: causal tile skip. KLIM: causal k-chunk limit.
#define STAGE_B 65536
#define HM_SMEM (3*STAGE_B + 1024)

template<int EPI, int CSKIP, int KLIM>
__global__ void __launch_bounds__(256, 1)
hmma_gemm(const uint4* __restrict__ Ah, const uint4* __restrict__ Al,
          const uint4* __restrict__ Bh, const uint4* __restrict__ Bl,
          float* __restrict__ C, const float* __restrict__ ADD,
          int nk, int ldc, int mtb, int ntb, long long sC, int cmode){
    extern __shared__ char dsm[];
    __shared__ __align__(8) unsigned long long s_mbar[3];
    int tnx = blockIdx.x, tmy = blockIdx.y, bz = blockIdx.z;
    if (CSKIP && tnx > tmy) return;
    int nkc = nk;
    if (KLIM) nkc = min(nk, 2*(tmy+1));
    int atr = bz*mtb + tmy;
    int btr = bz*ntb + tnx;
    long long offC = cmode ? ((long long)(bz>>4)*(long long)Sq*Dm + (long long)(bz&15)*DHd)
                           : (long long)bz*sC;
    float* Cb = C + offC + (size_t)tmy*128*ldc + (size_t)tnx*128;
    const float* Ab = (EPI==2) ? (ADD + offC + (size_t)tmy*128*ldc + (size_t)tnx*128) : nullptr;

    uint32_t ab = (smem_u32(dsm) + 1023) & ~1023u;
    int tid = threadIdx.x, wid = tid >> 5, l = tid & 31;
    int wm = wid >> 2, wn = wid & 3;      // 2 x 4 warp grid

    uint32_t mb[3];
    if (tid == 0){
        MB_INIT(smem_u32(&s_mbar[0]), 1);
        MB_INIT(smem_u32(&s_mbar[1]), 1);
        MB_INIT(smem_u32(&s_mbar[2]), 1);
    }
    mb[0] = smem_u32(&s_mbar[0]); mb[1] = smem_u32(&s_mbar[1]); mb[2] = smem_u32(&s_mbar[2]);
    __syncthreads();

    // prologue: fill up to 3 stages
    if (tid == 0){
        int pre = min(3, nkc);
        for (int c = 0; c < pre; c++){
            uint32_t base = ab + c*STAGE_B;
            MB_EXPECT_TX(mb[c], STAGE_B);
            BULK16K(base,         (const void*)(Ah + ((size_t)atr*nk + c)*1024), mb[c]);
            BULK16K(base + 16384, (const void*)(Al + ((size_t)atr*nk + c)*1024), mb[c]);
            BULK16K(base + 32768, (const void*)(Bh + ((size_t)btr*nk + c)*1024), mb[c]);
            BULK16K(base + 49152, (const void*)(Bl + ((size_t)btr*nk + c)*1024), mb[c]);
        }
    }

    // per-lane ldmatrix row offsets (bytes within 16KB block)
    int arow[4], brow[2];
    #pragma unroll
    for (int mt=0; mt<4; mt++)
        arow[mt] = (wm*64 + mt*16 + (l&7) + ((l>>3)&1)*8) * 128;
    #pragma unroll
    for (int p=0; p<2; p++)
        brow[p] = (wn*32 + p*16 + ((l>>4)&1)*8 + (l&7)) * 128;
    int akg = (l>>4)&1, bkg = (l>>3)&1, l7 = l&7;

    float acc[4][4][4];
    #pragma unroll
    for (int i=0;i<4;i++)
        #pragma unroll
        for (int j=0;j<4;j++)
            #pragma unroll
            for (int t=0;t<4;t++) acc[i][j][t] = 0.f;

    for (int c = 0; c < nkc; c++){
        int s = c % 3;
        MB_WAIT(mb[s], (c/3)&1);
        uint32_t aH = ab + s*STAGE_B, aL = aH + 16384, bH = aH + 32768, bL = aH + 49152;
        #pragma unroll
        for (int kk = 0; kk < 4; kk++){
            int kxA = ((kk*2 + akg) ^ l7) << 4;
            int kxB = ((kk*2 + bkg) ^ l7) << 4;
            uint32_t ah[4][4], al_[4][4], bhr[4][2], blr[4][2];
            #pragma unroll
            for (int mt=0; mt<4; mt++){
                LDSM4(ah[mt][0],ah[mt][1],ah[mt][2],ah[mt][3], aH + arow[mt] + kxA);
                LDSM4(al_[mt][0],al_[mt][1],al_[mt][2],al_[mt][3], aL + arow[mt] + kxA);
            }
            #pragma unroll
            for (int p=0; p<2; p++){
                LDSM4(bhr[2*p][0],bhr[2*p][1],bhr[2*p+1][0],bhr[2*p+1][1], bH + brow[p] + kxB);
                LDSM4(blr[2*p][0],blr[2*p][1],blr[2*p+1][0],blr[2*p+1][1], bL + brow[p] + kxB);
            }
            #pragma unroll
            for (int mt=0; mt<4; mt++)
                #pragma unroll
                for (int nt=0; nt<4; nt++){
                    MMA16816(acc[mt][nt], ah[mt],  bhr[nt][0], bhr[nt][1]);
                    MMA16816(acc[mt][nt], ah[mt],  blr[nt][0], blr[nt][1]);
                    MMA16816(acc[mt][nt], al_[mt], bhr[nt][0], bhr[nt][1]);
                }
        }
        __syncthreads();
        if (tid == 0 && c + 3 < nkc){
            int cc = c + 3;
            uint32_t base = ab + s*STAGE_B;
            MB_EXPECT_TX(mb[s], STAGE_B);
            BULK16K(base,         (const void*)(Ah + ((size_t)atr*nk + cc)*1024), mb[s]);
            BULK16K(base + 16384, (const void*)(Al + ((size_t)atr*nk + cc)*1024), mb[s]);
            BULK16K(base + 32768, (const void*)(Bh + ((size_t)btr*nk + cc)*1024), mb[s]);
            BULK16K(base + 49152, (const void*)(Bl + ((size_t)btr*nk + cc)*1024), mb[s]);
        }
    }

    // epilogue
    #pragma unroll
    for (int mt=0; mt<4; mt++){
        int r0 = wm*64 + mt*16 + (l>>2);
        #pragma unroll
        for (int nt=0; nt<4; nt++){
            int cc = wn*32 + nt*8 + (l&3)*2;
            float v0 = acc[mt][nt][0], v1 = acc[mt][nt][1];
            float v2 = acc[mt][nt][2], v3 = acc[mt][nt][3];
            if (EPI==1){
                v0 = 0.5f*v0*(1.f + erff(v0*0.7071067811865475f));
                v1 = 0.5f*v1*(1.f + erff(v1*0.7071067811865475f));
                v2 = 0.5f*v2*(1.f + erff(v2*0.7071067811865475f));
                v3 = 0.5f*v3*(1.f + erff(v3*0.7071067811865475f));
            }
            if (EPI==2){
                float2 x0 = *(const float2*)&Ab[(size_t)r0*ldc + cc];
                float2 x1 = *(const float2*)&Ab[(size_t)(r0+8)*ldc + cc];
                v0 += x0.x; v1 += x0.y; v2 += x1.x; v3 += x1.y;
            }
            *(float2*)&Cb[(size_t)r0*ldc + cc]     = make_float2(v0, v1);
            *(float2*)&Cb[(size_t)(r0+8)*ldc + cc] = make_float2(v2, v3);
        }
    }
}

// ================= launch =================
extern "C" void kernel_launch(void* const* d_in, const int* in_sizes, int n_in,
                              void* d_out, int out_size){
    const float* x      = (const float*)d_in[0];
    const float* scale1 = (const float*)d_in[2];
    const float* scale2 = (const float*)d_in[3];
    const float* Wq     = (const float*)d_in[4];
    const float* Wk     = (const float*)d_in[5];
    const float* Wv     = (const float*)d_in[6];
    const float* Wo     = (const float*)d_in[7];
    const float* headK  = (const float*)d_in[8];
    const float* W1     = (const float*)d_in[9];
    const float* W2     = (const float*)d_in[10];
    float* out = (float*)d_out;

    float *u,*v,*q,*k,*vv,*qlm,*kl,*probs,*attn,*ffn;
    cudaGetSymbolAddress((void**)&u,    g_u);
    cudaGetSymbolAddress((void**)&v,    g_v);
    cudaGetSymbolAddress((void**)&q,    g_q);
    cudaGetSymbolAddress((void**)&k,    g_k);
    cudaGetSymbolAddress((void**)&vv,   g_vv);
    cudaGetSymbolAddress((void**)&qlm,  g_qlm);
    cudaGetSymbolAddress((void**)&kl,   g_kl);
    cudaGetSymbolAddress((void**)&probs,g_probs);
    cudaGetSymbolAddress((void**)&attn, g_attn);
    cudaGetSymbolAddress((void**)&ffn,  g_ffn);

    uint4 *vh,*vl,*ath,*atl,*fh,*fl,*qh,*ql_,*kh,*klo,*ph,*pl,*vth,*vtl;
    uint4 *wqh,*wql,*wkh,*wkl,*wvh,*wvl,*woh,*wol,*w1h,*w1l,*w2h,*w2l;
    cudaGetSymbolAddress((void**)&vh,  g_vh);   cudaGetSymbolAddress((void**)&vl,  g_vl);
    cudaGetSymbolAddress((void**)&ath, g_ath);  cudaGetSymbolAddress((void**)&atl, g_atl);
    cudaGetSymbolAddress((void**)&fh,  g_fh);   cudaGetSymbolAddress((void**)&fl,  g_fl);
    cudaGetSymbolAddress((void**)&qh,  g_qh);   cudaGetSymbolAddress((void**)&ql_, g_ql);
    cudaGetSymbolAddress((void**)&kh,  g_kh);   cudaGetSymbolAddress((void**)&klo, g_klo);
    cudaGetSymbolAddress((void**)&ph,  g_ph);   cudaGetSymbolAddress((void**)&pl,  g_pl);
    cudaGetSymbolAddress((void**)&vth, g_vth);  cudaGetSymbolAddress((void**)&vtl, g_vtl);
    cudaGetSymbolAddress((void**)&wqh, g_WqTh); cudaGetSymbolAddress((void**)&wql, g_WqTl);
    cudaGetSymbolAddress((void**)&wkh, g_WkTh); cudaGetSymbolAddress((void**)&wkl, g_WkTl);
    cudaGetSymbolAddress((void**)&wvh, g_WvTh); cudaGetSymbolAddress((void**)&wvl, g_WvTl);
    cudaGetSymbolAddress((void**)&woh, g_WoTh); cudaGetSymbolAddress((void**)&wol, g_WoTl);
    cudaGetSymbolAddress((void**)&w1h, g_W1Th); cudaGetSymbolAddress((void**)&w1l, g_W1Tl);
    cudaGetSymbolAddress((void**)&w2h, g_W2Th); cudaGetSymbolAddress((void**)&w2l, g_W2Tl);

    cudaFuncSetAttribute(hmma_gemm<0,0,0>, cudaFuncAttributeMaxDynamicSharedMemorySize, HM_SMEM);
    cudaFuncSetAttribute(hmma_gemm<1,0,0>, cudaFuncAttributeMaxDynamicSharedMemorySize, HM_SMEM);
    cudaFuncSetAttribute(hmma_gemm<2,0,0>, cudaFuncAttributeMaxDynamicSharedMemorySize, HM_SMEM);
    cudaFuncSetAttribute(hmma_gemm<0,1,0>, cudaFuncAttributeMaxDynamicSharedMemorySize, HM_SMEM);
    cudaFuncSetAttribute(hmma_gemm<0,0,1>, cudaFuncAttributeMaxDynamicSharedMemorySize, HM_SMEM);

    // 0) weight splits (transposed to [N,K] TS)
    k_split_wT<<<dim3(Dm/128,  Dm/64,  1),256>>>(Wq, wqh, wql, Dm, Dm, Dm, 0, 0);
    k_split_wT<<<dim3(Dm/128,  Dm/64,  1),256>>>(Wk, wkh, wkl, Dm, Dm, Dm, 0, 0);
    k_split_wT<<<dim3(Dm/128,  Dm/64,  1),256>>>(Wv, wvh, wvl, Dm, Dm, Dm, 0, 0);
    k_split_wT<<<dim3(Dm/128,  Dm/64,  1),256>>>(Wo, woh, wol, Dm, Dm, Dm, 0, 0);
    k_split_wT<<<dim3(DFFd/128,Dm/64,  1),256>>>(W1, w1h, w1l, Dm, DFFd, DFFd, 0, 0);
    k_split_wT<<<dim3(Dm/128,  DFFd/64,1),256>>>(W2, w2h, w2l, DFFd, Dm, Dm, 0, 0);

    // 1) u0 = log(x); v1 = norm1(u0); split
    k_lognorm1<<<ROWS,256>>>(x, scale1, u, v);
    k_split_act<<<dim3(ROWS/128, Dm/64),256>>>(v, vh, vl, Dm, 0);

    // 2) QKV projections
    dim3 gQ(Dm/128, ROWS/128);
    hmma_gemm<0,0,0><<<gQ,256,HM_SMEM>>>(vh, vl, wqh, wql, q,  nullptr, Dm/64, Dm, 0,0,0,0);
    hmma_gemm<0,0,0><<<gQ,256,HM_SMEM>>>(vh, vl, wkh, wkl, k,  nullptr, Dm/64, Dm, 0,0,0,0);
    hmma_gemm<0,0,0><<<gQ,256,HM_SMEM>>>(vh, vl, wvh, wvl, vv, nullptr, Dm/64, Dm, 0,0,0,0);

    // 3) lorentz lift (192-padded) + splits
    k_qlkl<<<dim3(ROWS,Hh,2),128>>>(headK, q, k, qlm, kl);
    k_split_act<<<dim3(BHn*Sq/128, KLQ/64),256>>>(qlm, qh, ql_, KLQ, 0);
    k_split_act<<<dim3(BHn*Sq/128, KLQ/64),256>>>(kl,  kh, klo, KLQ, 0);

    // 4) causal scores: probs[bh] = qlm @ kl^T  (tile-skip above diagonal)
    hmma_gemm<0,1,0><<<dim3(Sq/128, Sq/128, BHn),256,HM_SMEM>>>(
        qh, ql_, kh, klo, probs, nullptr, KLQ/64, Sq, Sq/128, Sq/128, (long long)Sq*Sq, 0);

    // 5) causal softmax (zero-fills k>q)
    k_softmax<<<BHn*Sq,256>>>(probs);

    // 6) PV: split probs (causal tile skip) + per-head V^T split, then GEMM (k-limited)
    k_split_act<<<dim3(BHn*Sq/128, Sq/64),256>>>(probs, ph, pl, Sq, 1);
    k_split_wT<<<dim3(1, Sq/64, BHn),256>>>(vv, vth, vtl, Sq, DHd, Dm, 1, (long long)(Sq/64)*1024);
    hmma_gemm<0,0,1><<<dim3(1, Sq/128, BHn),256,HM_SMEM>>>(
        ph, pl, vth, vtl, attn, nullptr, Sq/64, Dm, Sq/128, 1, 0, 1);

    // 7) Wo projection + residual: u += attn@Wo
    k_split_act<<<dim3(ROWS/128, Dm/64),256>>>(attn, ath, atl, Dm, 0);
    hmma_gemm<2,0,0><<<gQ,256,HM_SMEM>>>(ath, atl, woh, wol, u, u, Dm/64, Dm, 0,0,0,0);

    // 8) v2 = norm2(u1); split
    k_norm2<<<ROWS,256>>>(u, scale2, v);
    k_split_act<<<dim3(ROWS/128, Dm/64),256>>>(v, vh, vl, Dm, 0);

    // 9) FFN up + exact gelu
    hmma_gemm<1,0,0><<<dim3(DFFd/128, ROWS/128),256,HM_SMEM>>>(
        vh, vl, w1h, w1l, ffn, nullptr, Dm/64, DFFd, 0,0,0,0);

    // 10) FFN down + residual: u += gelu@W2
    k_split_act<<<dim3(ROWS/128, DFFd/64),256>>>(ffn, fh, fl, DFFd, 0);
    hmma_gemm<2,0,0><<<gQ,256,HM_SMEM>>>(fh, fl, w2h, w2l, u, u, DFFd/64, Dm, 0,0,0,0);

    // 11) out = exp_map(u2)
    k_expmap<<<ROWS,256>>>(u, out);
}

// round 6
// speedup vs baseline: 3.3215x; 1.0560x over previous
#include <cuda_runtime.h>
#include <cuda_bf16.h>
#include <math.h>
#include <stdint.h>

// Problem dims (fixed)
#define Bz   2
#define Sq   2048
#define Dm   2048
#define Hh   16
#define DHd  128
#define DFFd 8192
#define ROWS (Bz*Sq)       // 4096
#define BHn  (Bz*Hh)       // 32
#define EPSn 1e-6f

// ================= PTX helpers (baseline compute_103 features only) =================
__device__ __forceinline__ uint32_t smem_u32(const void* p){
    uint32_t r;
    asm("{ .reg .u64 t; cvta.to.shared.u64 t, %1; cvt.u32.u64 %0, t; }" : "=r"(r) : "l"(p));
    return r;
}
#define MB_INIT(addr,cnt) asm volatile("mbarrier.init.shared.b64 [%0], %1;"::"r"(addr),"r"(cnt):"memory")
#define MB_EXPECT_TX(addr,tx) asm volatile("mbarrier.arrive.expect_tx.shared.b64 _, [%0], %1;"::"r"(addr),"r"(tx):"memory")
#define MB_WAIT(addr, ph) do { \
    asm volatile("{\n\t.reg .pred P1;\n\tWL%=:\n\t" \
        "mbarrier.try_wait.parity.acquire.cta.shared::cta.b64 P1, [%0], %1, 0x989680;\n\t" \
        "@P1 bra.uni WD%=;\n\tbra.uni WL%=;\n\tWD%=:\n\t}" \
        :: "r"(addr), "r"(ph) : "memory"); } while(0)
#define BULK16K(dst, src, mb) asm volatile( \
    "cp.async.bulk.shared::cta.global.mbarrier::complete_tx::bytes [%0], [%1], %2, [%3];" \
    :: "r"(dst), "l"(src), "r"(16384), "r"(mb) : "memory")
#define LDSM4(r0,r1,r2,r3,addr) asm volatile( \
    "ldmatrix.sync.aligned.m8n8.x4.shared.b16 {%0,%1,%2,%3},[%4];" \
    : "=r"(r0),"=r"(r1),"=r"(r2),"=r"(r3) : "r"(addr))
#define MMA16816(c, a, b0, b1) asm volatile( \
    "mma.sync.aligned.m16n8k16.row.col.f32.bf16.bf16.f32 " \
    "{%0,%1,%2,%3},{%4,%5,%6,%7},{%8,%9},{%0,%1,%2,%3};" \
    : "+f"((c)[0]),"+f"((c)[1]),"+f"((c)[2]),"+f"((c)[3]) \
    : "r"((a)[0]),"r"((a)[1]),"r"((a)[2]),"r"((a)[3]), "r"(b0),"r"(b1))
#define SWZ(o) ((o) ^ (((o)>>3)&0x70))

// ================= scratch (device globals) =================
__device__ float g_u   [(size_t)ROWS*Dm];
__device__ float g_q   [(size_t)ROWS*Dm];
__device__ float g_k   [(size_t)ROWS*Dm];
__device__ float g_vv  [(size_t)ROWS*Dm];
__device__ float g_probs[(size_t)BHn*Sq*Sq];    // raw scores (fp32, causal tiles only)
__device__ float g_ax  [(size_t)BHn*Sq];        // -gsc*x0_q
__device__ float g_bx  [(size_t)BHn*Sq];        // x0_k

// bf16 hi/lo tiled-swizzled (TS) operands, uint4 granules (= elems/8).
// TS: [R,C] as tiles 128r x 64c bf16; tile (tr,kc) at granule (tr*(C/64)+kc)*1024,
// interior: granule index = SWZ(r*128 + g*16)>>4  (g = col/8).
__device__ uint4 g_vh  [(size_t)ROWS*Dm/8],   g_vl  [(size_t)ROWS*Dm/8];
__device__ uint4 g_ath [(size_t)ROWS*Dm/8],   g_atl [(size_t)ROWS*Dm/8];
__device__ uint4 g_fh  [(size_t)ROWS*DFFd/8], g_fl  [(size_t)ROWS*DFFd/8];
__device__ uint4 g_qh  [(size_t)BHn*Sq*DHd/8], g_ql [(size_t)BHn*Sq*DHd/8];
__device__ uint4 g_kh  [(size_t)BHn*Sq*DHd/8], g_klo[(size_t)BHn*Sq*DHd/8];
__device__ uint4 g_ph  [(size_t)BHn*Sq*Sq/8],  g_pl [(size_t)BHn*Sq*Sq/8];
__device__ uint4 g_vth [(size_t)BHn*DHd*Sq/8], g_vtl[(size_t)BHn*DHd*Sq/8];
__device__ uint4 g_WqTh[(size_t)Dm*Dm/8], g_WqTl[(size_t)Dm*Dm/8];
__device__ uint4 g_WkTh[(size_t)Dm*Dm/8], g_WkTl[(size_t)Dm*Dm/8];
__device__ uint4 g_WvTh[(size_t)Dm*Dm/8], g_WvTl[(size_t)Dm*Dm/8];
__device__ uint4 g_WoTh[(size_t)Dm*Dm/8], g_WoTl[(size_t)Dm*Dm/8];
__device__ uint4 g_W1Th[(size_t)Dm*DFFd/8], g_W1Tl[(size_t)Dm*DFFd/8];
__device__ uint4 g_W2Th[(size_t)Dm*DFFd/8], g_W2Tl[(size_t)Dm*DFFd/8];

union Pack8 { __nv_bfloat16 b[8]; uint4 v; };

// ================= reductions =================
__device__ __forceinline__ float warpSum(float v){
    #pragma unroll
    for (int o=16;o;o>>=1) v += __shfl_xor_sync(0xffffffffu, v, o);
    return v;
}
__device__ __forceinline__ float warpMax(float v){
    #pragma unroll
    for (int o=16;o;o>>=1) v = fmaxf(v, __shfl_xor_sync(0xffffffffu, v, o));
    return v;
}
__device__ __forceinline__ float blockSum(float v){
    __shared__ float sh[32];
    int lane = threadIdx.x & 31, w = threadIdx.x >> 5, nw = (blockDim.x + 31) >> 5;
    v = warpSum(v);
    __syncthreads();
    if (lane == 0) sh[w] = v;
    __syncthreads();
    float r = (lane < nw) ? sh[lane] : 0.f;
    return warpSum(r);
}
__device__ __forceinline__ float blockMax(float v){
    __shared__ float sh[32];
    int lane = threadIdx.x & 31, w = threadIdx.x >> 5, nw = (blockDim.x + 31) >> 5;
    v = warpMax(v);
    __syncthreads();
    if (lane == 0) sh[w] = v;
    __syncthreads();
    float r = (lane < nw) ? sh[lane] : -1e30f;
    return warpMax(r);
}

__device__ __forceinline__ void split_pack(const float* xs, Pack8& H, Pack8& L){
    #pragma unroll
    for (int j=0;j<8;j++){
        __nv_bfloat16 h = __float2bfloat16(xs[j]);
        H.b[j] = h;
        L.b[j] = __float2bfloat16(xs[j] - __bfloat162float(h));
    }
}

// ================= fused elementwise kernels =================
// u0 = log_map(x); v1 = norm; write u fp32 + vh/vl TS directly. 256 thr/row, thread t -> cols [8t,8t+8)
// NOTE: x rows have stride 2049 floats (+1 offset) -> NOT 16B aligned; load scalars.
__global__ void k_lognorm1(const float* __restrict__ x, const float* __restrict__ scale,
                           float* __restrict__ u, uint4* __restrict__ vh, uint4* __restrict__ vl){
    int row = blockIdx.x, t = threadIdx.x;
    const float* xr = x + (size_t)row*(Dm+1) + 1 + t*8;
    float xs[8];
    #pragma unroll
    for (int j=0;j<8;j++) xs[j] = xr[j];
    float ss = 0.f;
    #pragma unroll
    for (int j=0;j<8;j++) ss += xs[j]*xs[j];
    float n2 = blockSum(ss);
    float a  = sqrtf(n2);
    float f  = (a < 1e-6f) ? (1.f - a*a*(1.f/6.f)) : (asinhf(a)/fmaxf(a,1e-12f));
    float rms = sqrtf(f*f*n2*(1.f/(float)Dm) + EPSn);
    float inv = 1.f/rms;
    float4 S0 = *(const float4*)(scale + t*8), S1 = *(const float4*)(scale + t*8 + 4);
    float sc[8] = {S0.x,S0.y,S0.z,S0.w,S1.x,S1.y,S1.z,S1.w};
    float us[8], vs[8];
    #pragma unroll
    for (int j=0;j<8;j++){ us[j] = f*xs[j]; vs[j] = sc[j]*us[j]*inv; }
    float* ur = u + (size_t)row*Dm + t*8;
    *(float4*)ur     = make_float4(us[0],us[1],us[2],us[3]);
    *(float4*)(ur+4) = make_float4(us[4],us[5],us[6],us[7]);
    Pack8 H, L; split_pack(vs, H, L);
    uint32_t tr = row>>7, rl = row&127;
    int kc = t>>3, gg = t&7;
    size_t blk = (((size_t)tr*(Dm/64) + kc)<<10) + (SWZ((uint32_t)(rl*128 + gg*16))>>4);
    vh[blk] = H.v; vl[blk] = L.v;
}

// v2 = norm2(u): reads u fp32, writes vh/vl TS
__global__ void k_norm2(const float* __restrict__ u, const float* __restrict__ scale,
                        uint4* __restrict__ vh, uint4* __restrict__ vl){
    int row = blockIdx.x, t = threadIdx.x;
    const float* ur = u + (size_t)row*Dm + t*8;
    float4 A = *(const float4*)ur, B = *(const float4*)(ur+4);
    float xs[8] = {A.x,A.y,A.z,A.w,B.x,B.y,B.z,B.w};
    float ss = 0.f;
    #pragma unroll
    for (int j=0;j<8;j++) ss += xs[j]*xs[j];
    float n2 = blockSum(ss);
    float rms = sqrtf(n2*(1.f/(float)Dm) + EPSn);
    float inv = 1.f/rms;
    float4 S0 = *(const float4*)(scale + t*8), S1 = *(const float4*)(scale + t*8 + 4);
    float sc[8] = {S0.x,S0.y,S0.z,S0.w,S1.x,S1.y,S1.z,S1.w};
    float vs[8];
    #pragma unroll
    for (int j=0;j<8;j++) vs[j] = sc[j]*xs[j]*inv;
    Pack8 H, L; split_pack(vs, H, L);
    uint32_t tr = row>>7, rl = row&127;
    int kc = t>>3, gg = t&7;
    size_t blk = (((size_t)tr*(Dm/64) + kc)<<10) + (SWZ((uint32_t)(rl*128 + gg*16))>>4);
    vh[blk] = H.v; vl[blk] = L.v;
}

// per-head lorentz lift: q,k (fp32) -> TS hi/lo (128 dims) + rank-1 vectors ax,bx.
// grid (ROWS, Hh), 128 thr.
__global__ void k_qlkl(const float* __restrict__ headK,
                       const float* __restrict__ qsrc, const float* __restrict__ ksrc,
                       uint4* __restrict__ qh, uint4* __restrict__ ql,
                       uint4* __restrict__ kh, uint4* __restrict__ klo,
                       float* __restrict__ ax, float* __restrict__ bx){
    int bs = blockIdx.x, h = blockIdx.y, t = threadIdx.x;
    float qv = qsrc[(size_t)bs*Dm + h*DHd + t];
    float kv = ksrc[(size_t)bs*Dm + h*DHd + t];
    float n2q = blockSum(qv*qv);
    float n2k = blockSum(kv*kv);
    float Kh = headK[h]; float sK = sqrtf(-Kh);
    float aq = sK*sqrtf(n2q);
    float sincq = (aq<1e-6f)?(1.f+aq*aq*(1.f/6.f)):(sinhf(aq)/fmaxf(aq,1e-12f));
    float x0q = sqrtf(-1.f/Kh + sincq*sincq*n2q);
    float ak = sK*sqrtf(n2k);
    float sinck = (ak<1e-6f)?(1.f+ak*ak*(1.f/6.f)):(sinhf(ak)/fmaxf(ak,1e-12f));
    float x0k = sqrtf(-1.f/Kh + sinck*sinck*n2k);
    const float gsc = 0.1767766952966369f;    // 2/sqrt(128)
    __shared__ float sq[128], sk[128];
    sq[t] = gsc*sincq*qv;
    sk[t] = sinck*kv;
    int b = bs >> 11, s = bs & 2047;
    size_t R = ((size_t)(b*Hh + h)<<11) + s;
    if (t==0){ ax[R] = -gsc*x0q; bx[R] = x0k; }
    __syncthreads();
    uint32_t tr = (uint32_t)(R>>7), rl = (uint32_t)(R&127);
    int which = t>>4, g = t&15;
    if (which < 4){
        int kc = g>>3, gg = g&7;
        size_t blk = (((size_t)tr*2 + kc)<<10) + (SWZ(rl*128 + gg*16)>>4);
        const float* sv = (which<2) ? sq : sk;
        Pack8 p;
        #pragma unroll
        for (int j=0;j<8;j++){
            float xv = sv[g*8+j];
            __nv_bfloat16 hh = __float2bfloat16(xv);
            p.b[j] = (which&1) ? __float2bfloat16(xv - __bfloat162float(hh)) : hh;
        }
        uint4* dst = (which==0)?qh:(which==1)?ql:(which==2)?kh:klo;
        dst[blk] = p.v;
    }
}

// causal softmax fused with bf16 hi/lo split: reads raw scores (fp32),
// writes ph/pl TS only for granules within causal tile boundary.
// grid (BHn*Sq), 256 thr; thread t -> granule t (cols 8t..8t+7).
__global__ void k_softmax(const float* __restrict__ probs,
                          uint4* __restrict__ ph, uint4* __restrict__ pl){
    int row = blockIdx.x;
    int qi = row & 2047;
    const float* p = probs + (size_t)row*Sq;
    int t = threadIdx.x;
    int lastg = ((qi>>7)+1)<<4;       // granules in causal tiles
    bool act = t < lastg;
    float vals[8];
    float m = -1e30f;
    if (act){
        float4 A = *(const float4*)(p + t*8), B = *(const float4*)(p + t*8 + 4);
        vals[0]=A.x; vals[1]=A.y; vals[2]=A.z; vals[3]=A.w;
        vals[4]=B.x; vals[5]=B.y; vals[6]=B.z; vals[7]=B.w;
        #pragma unroll
        for (int j=0;j<8;j++){
            if (t*8+j > qi) vals[j] = -1e30f;
            m = fmaxf(m, vals[j]);
        }
    } else {
        #pragma unroll
        for (int j=0;j<8;j++) vals[j] = -1e30f;
    }
    m = blockMax(m);
    float s = 0.f;
    #pragma unroll
    for (int j=0;j<8;j++){
        float e = (vals[j] > -1e29f) ? expf(vals[j]-m) : 0.f;
        vals[j] = e; s += e;
    }
    s = blockSum(s);
    float inv = 1.f/s;
    if (act){
        float ps[8];
        #pragma unroll
        for (int j=0;j<8;j++) ps[j] = vals[j]*inv;
        Pack8 H, L; split_pack(ps, H, L);
        uint32_t tr = (uint32_t)row>>7, rl = (uint32_t)row&127;
        int kc = t>>3, gg = t&7;
        size_t blk = (((size_t)tr*(Sq/64) + kc)<<10) + (SWZ(rl*128 + gg*16)>>4);
        ph[blk] = H.v; pl[blk] = L.v;
    }
}

__global__ void k_expmap(const float* __restrict__ u, float* __restrict__ out){
    int row = blockIdx.x, tid = threadIdx.x;
    const float* ur = u + (size_t)row*Dm;
    float loc[8]; float s = 0.f;
    #pragma unroll
    for (int j=0;j<8;j++){ float t = ur[tid + j*256]; loc[j]=t; s += t*t; }
    float n2 = blockSum(s);
    float a = sqrtf(n2);
    float sinc = (a < 1e-6f) ? (1.f + a*a*(1.f/6.f)) : (sinhf(a)/fmaxf(a,1e-12f));
    float x0 = sqrtf(1.f + sinc*sinc*n2);
    float* o = out + (size_t)row*(Dm+1);
    if (tid==0) o[0] = x0;
    #pragma unroll
    for (int j=0;j<8;j++){ int d = tid + j*256; o[1+d] = sinc*loc[j]; }
}

// ================= weight / V-transpose split =================
// W[K,N] (row stride ld) -> WT[N,K] TS. grid (N/128, K/64, nz), 256 thr.
__global__ void k_split_wT(const float* __restrict__ W, uint4* __restrict__ Hi,
                           uint4* __restrict__ Lo, int K, int N, int ld,
                           int hmode, long long outzG){
    __shared__ float s[64][129];
    int tr = blockIdx.x, kc = blockIdx.y, bz = blockIdx.z;
    int ntc = K >> 6;
    const float* Wb = W + (hmode ? ((long long)(bz>>4)*(long long)Sq*Dm + (long long)(bz&15)*DHd) : 0);
    Hi += (size_t)bz*outzG; Lo += (size_t)bz*outzG;
    int n0 = tr*128, k0 = kc*64;
    int col = threadIdx.x & 127, r0 = threadIdx.x >> 7;
    #pragma unroll
    for (int i=0;i<32;i++){
        int r = r0 + i*2;
        s[r][col] = Wb[(size_t)(k0+r)*ld + n0 + col];
    }
    __syncthreads();
    size_t blk = ((size_t)tr*ntc + kc)*1024;
    #pragma unroll
    for (int i=0;i<4;i++){
        int gid = threadIdx.x + i*256;
        int nl = gid >> 3, g = gid & 7;
        Pack8 uh, ul;
        #pragma unroll
        for (int j=0;j<8;j++){
            float x = s[g*8+j][nl];
            __nv_bfloat16 h = __float2bfloat16(x);
            uh.b[j] = h;
            ul.b[j] = __float2bfloat16(x - __bfloat162float(h));
        }
        uint32_t off = SWZ((uint32_t)(nl*128 + g*16)) >> 4;
        Hi[blk + off] = uh.v;
        Lo[blk + off] = ul.v;
    }
}

// ================= HMMA bf16x3 pipelined GEMM =================
// EPI: 0 fp32 out; 2 fp32 += ADD; 3 TS hi/lo out; 4 gelu + TS hi/lo out; 5 fp32 out + rank-1 add.
// CSKIP: causal tile skip. KLIM: causal k-chunk limit.
#define STAGE_B 65536
#define HM_SMEM (3*STAGE_B + 1024)

template<int EPI, int CSKIP, int KLIM>
__global__ void __launch_bounds__(256, 1)
hmma_gemm(const uint4* __restrict__ Ah, const uint4* __restrict__ Al,
          const uint4* __restrict__ Bh, const uint4* __restrict__ Bl,
          float* __restrict__ C, const float* __restrict__ ADD,
          uint4* __restrict__ OHi, uint4* __restrict__ OLo,
          const float* __restrict__ AX, const float* __restrict__ BX,
          int nk, int ldc, int ntc, int mtb, int ntb, long long sC, int cmode){
    extern __shared__ char dsm[];
    __shared__ __align__(8) unsigned long long s_mbar[3];
    int tnx = blockIdx.x, tmy = blockIdx.y, bz = blockIdx.z;
    if (CSKIP && tnx > tmy) return;
    int nkc = nk;
    if (KLIM) nkc = min(nk, 2*(tmy+1));
    int atr = bz*mtb + tmy;
    int btr = bz*ntb + tnx;

    uint32_t ab = (smem_u32(dsm) + 1023) & ~1023u;
    int tid = threadIdx.x, wid = tid >> 5, l = tid & 31;
    int wm = wid >> 2, wn = wid & 3;      // 2 x 4 warp grid

    uint32_t mb[3];
    if (tid == 0){
        MB_INIT(smem_u32(&s_mbar[0]), 1);
        MB_INIT(smem_u32(&s_mbar[1]), 1);
        MB_INIT(smem_u32(&s_mbar[2]), 1);
    }
    mb[0] = smem_u32(&s_mbar[0]); mb[1] = smem_u32(&s_mbar[1]); mb[2] = smem_u32(&s_mbar[2]);
    __syncthreads();

    if (tid == 0){
        int pre = min(3, nkc);
        for (int c = 0; c < pre; c++){
            uint32_t base = ab + c*STAGE_B;
            MB_EXPECT_TX(mb[c], STAGE_B);
            BULK16K(base,         (const void*)(Ah + ((size_t)atr*nk + c)*1024), mb[c]);
            BULK16K(base + 16384, (const void*)(Al + ((size_t)atr*nk + c)*1024), mb[c]);
            BULK16K(base + 32768, (const void*)(Bh + ((size_t)btr*nk + c)*1024), mb[c]);
            BULK16K(base + 49152, (const void*)(Bl + ((size_t)btr*nk + c)*1024), mb[c]);
        }
    }

    int arow[4], brow[2];
    #pragma unroll
    for (int mt=0; mt<4; mt++)
        arow[mt] = (wm*64 + mt*16 + (l&7) + ((l>>3)&1)*8) * 128;
    #pragma unroll
    for (int p=0; p<2; p++)
        brow[p] = (wn*32 + p*16 + ((l>>4)&1)*8 + (l&7)) * 128;
    int akg = (l>>4)&1, bkg = (l>>3)&1, l7 = l&7;

    float acc[4][4][4];
    #pragma unroll
    for (int i=0;i<4;i++)
        #pragma unroll
        for (int j=0;j<4;j++)
            #pragma unroll
            for (int t=0;t<4;t++) acc[i][j][t] = 0.f;

    for (int c = 0; c < nkc; c++){
        int s = c % 3;
        MB_WAIT(mb[s], (c/3)&1);
        uint32_t aH = ab + s*STAGE_B, aL = aH + 16384, bH = aH + 32768, bL = aH + 49152;
        #pragma unroll
        for (int kk = 0; kk < 4; kk++){
            int kxA = ((kk*2 + akg) ^ l7) << 4;
            int kxB = ((kk*2 + bkg) ^ l7) << 4;
            uint32_t ah[4][4], al_[4][4], bhr[4][2], blr[4][2];
            #pragma unroll
            for (int mt=0; mt<4; mt++){
                LDSM4(ah[mt][0],ah[mt][1],ah[mt][2],ah[mt][3], aH + arow[mt] + kxA);
                LDSM4(al_[mt][0],al_[mt][1],al_[mt][2],al_[mt][3], aL + arow[mt] + kxA);
            }
            #pragma unroll
            for (int p=0; p<2; p++){
                LDSM4(bhr[2*p][0],bhr[2*p][1],bhr[2*p+1][0],bhr[2*p+1][1], bH + brow[p] + kxB);
                LDSM4(blr[2*p][0],blr[2*p][1],blr[2*p+1][0],blr[2*p+1][1], bL + brow[p] + kxB);
            }
            #pragma unroll
            for (int mt=0; mt<4; mt++)
                #pragma unroll
                for (int nt=0; nt<4; nt++){
                    MMA16816(acc[mt][nt], ah[mt],  bhr[nt][0], bhr[nt][1]);
                    MMA16816(acc[mt][nt], ah[mt],  blr[nt][0], blr[nt][1]);
                    MMA16816(acc[mt][nt], al_[mt], bhr[nt][0], bhr[nt][1]);
                }
        }
        __syncthreads();
        if (tid == 0 && c + 3 < nkc){
            int cc = c + 3;
            uint32_t base = ab + s*STAGE_B;
            MB_EXPECT_TX(mb[s], STAGE_B);
            BULK16K(base,         (const void*)(Ah + ((size_t)atr*nk + cc)*1024), mb[s]);
            BULK16K(base + 16384, (const void*)(Al + ((size_t)atr*nk + cc)*1024), mb[s]);
            BULK16K(base + 32768, (const void*)(Bh + ((size_t)btr*nk + cc)*1024), mb[s]);
            BULK16K(base + 49152, (const void*)(Bl + ((size_t)btr*nk + cc)*1024), mb[s]);
        }
    }

    // -------- epilogue --------
    if (EPI == 3 || EPI == 4){
        int otr, ocol0;
        if (cmode){ otr = (bz>>4)*(Sq/128) + tmy; ocol0 = (bz&15)*DHd + tnx*128; }
        else      { otr = tmy;                    ocol0 = tnx*128; }
        char* HiB = (char*)OHi;
        char* LoB = (char*)OLo;
        #pragma unroll
        for (int mt=0; mt<4; mt++){
            int r0 = wm*64 + mt*16 + (l>>2);
            uint32_t ro0 = (uint32_t)(r0*128), ro1 = (uint32_t)((r0+8)*128);
            #pragma unroll
            for (int nt=0; nt<4; nt++){
                int col = ocol0 + wn*32 + nt*8 + (l&3)*2;
                float v0 = acc[mt][nt][0], v1 = acc[mt][nt][1];
                float v2 = acc[mt][nt][2], v3 = acc[mt][nt][3];
                if (EPI == 4){
                    v0 = 0.5f*v0*(1.f + erff(v0*0.7071067811865475f));
                    v1 = 0.5f*v1*(1.f + erff(v1*0.7071067811865475f));
                    v2 = 0.5f*v2*(1.f + erff(v2*0.7071067811865475f));
                    v3 = 0.5f*v3*(1.f + erff(v3*0.7071067811865475f));
                }
                int kcn = col>>6, g = (col>>3)&7, w2 = (col&7)*2;
                size_t blkB = (((size_t)otr*ntc + kcn)<<14);
                uint32_t o0 = SWZ(ro0 + g*16) + w2;
                uint32_t o1 = SWZ(ro1 + g*16) + w2;
                __nv_bfloat16 h0 = __float2bfloat16(v0), h1 = __float2bfloat16(v1);
                __nv_bfloat16 h2 = __float2bfloat16(v2), h3 = __float2bfloat16(v3);
                __nv_bfloat16 l0 = __float2bfloat16(v0 - __bfloat162float(h0));
                __nv_bfloat16 l1 = __float2bfloat16(v1 - __bfloat162float(h1));
                __nv_bfloat16 l2 = __float2bfloat16(v2 - __bfloat162float(h2));
                __nv_bfloat16 l3 = __float2bfloat16(v3 - __bfloat162float(h3));
                *(uint32_t*)(HiB + blkB + o0) = (uint32_t)__bfloat16_as_ushort(h0) | ((uint32_t)__bfloat16_as_ushort(h1)<<16);
                *(uint32_t*)(LoB + blkB + o0) = (uint32_t)__bfloat16_as_ushort(l0) | ((uint32_t)__bfloat16_as_ushort(l1)<<16);
                *(uint32_t*)(HiB + blkB + o1) = (uint32_t)__bfloat16_as_ushort(h2) | ((uint32_t)__bfloat16_as_ushort(h3)<<16);
                *(uint32_t*)(LoB + blkB + o1) = (uint32_t)__bfloat16_as_ushort(l2) | ((uint32_t)__bfloat16_as_ushort(l3)<<16);
            }
        }
    } else {
        long long offC = cmode ? ((long long)(bz>>4)*(long long)Sq*Dm + (long long)(bz&15)*DHd)
                               : (long long)bz*sC;
        float* Cb = C + offC + (size_t)tmy*128*ldc + (size_t)tnx*128;
        const float* Ab = (EPI==2) ? (ADD + offC + (size_t)tmy*128*ldc + (size_t)tnx*128) : nullptr;
        const float* axp = (EPI==5) ? (AX + (size_t)bz*Sq + tmy*128) : nullptr;
        const float* bxp = (EPI==5) ? (BX + (size_t)bz*Sq + tnx*128) : nullptr;
        #pragma unroll
        for (int mt=0; mt<4; mt++){
            int r0 = wm*64 + mt*16 + (l>>2);
            float a0 = 0.f, a1 = 0.f;
            if (EPI==5){ a0 = axp[r0]; a1 = axp[r0+8]; }
            #pragma unroll
            for (int nt=0; nt<4; nt++){
                int cc = wn*32 + nt*8 + (l&3)*2;
                float v0 = acc[mt][nt][0], v1 = acc[mt][nt][1];
                float v2 = acc[mt][nt][2], v3 = acc[mt][nt][3];
                if (EPI==5){
                    float b0 = bxp[cc], b1 = bxp[cc+1];
                    v0 += a0*b0; v1 += a0*b1; v2 += a1*b0; v3 += a1*b1;
                }
                if (EPI==2){
                    float2 x0 = *(const float2*)&Ab[(size_t)r0*ldc + cc];
                    float2 x1 = *(const float2*)&Ab[(size_t)(r0+8)*ldc + cc];
                    v0 += x0.x; v1 += x0.y; v2 += x1.x; v3 += x1.y;
                }
                *(float2*)&Cb[(size_t)r0*ldc + cc]     = make_float2(v0, v1);
                *(float2*)&Cb[(size_t)(r0+8)*ldc + cc] = make_float2(v2, v3);
            }
        }
    }
}

// ================= launch =================
extern "C" void kernel_launch(void* const* d_in, const int* in_sizes, int n_in,
                              void* d_out, int out_size){
    const float* x      = (const float*)d_in[0];
    const float* scale1 = (const float*)d_in[2];
    const float* scale2 = (const float*)d_in[3];
    const float* Wq     = (const float*)d_in[4];
    const float* Wk     = (const float*)d_in[5];
    const float* Wv     = (const float*)d_in[6];
    const float* Wo     = (const float*)d_in[7];
    const float* headK  = (const float*)d_in[8];
    const float* W1     = (const float*)d_in[9];
    const float* W2     = (const float*)d_in[10];
    float* out = (float*)d_out;

    float *u,*q,*k,*vv,*probs,*ax,*bx;
    cudaGetSymbolAddress((void**)&u,    g_u);
    cudaGetSymbolAddress((void**)&q,    g_q);
    cudaGetSymbolAddress((void**)&k,    g_k);
    cudaGetSymbolAddress((void**)&vv,   g_vv);
    cudaGetSymbolAddress((void**)&probs,g_probs);
    cudaGetSymbolAddress((void**)&ax,   g_ax);
    cudaGetSymbolAddress((void**)&bx,   g_bx);

    uint4 *vh,*vl,*ath,*atl,*fh,*fl,*qh,*ql_,*kh,*klo,*ph,*pl,*vth,*vtl;
    uint4 *wqh,*wql,*wkh,*wkl,*wvh,*wvl,*woh,*wol,*w1h,*w1l,*w2h,*w2l;
    cudaGetSymbolAddress((void**)&vh,  g_vh);   cudaGetSymbolAddress((void**)&vl,  g_vl);
    cudaGetSymbolAddress((void**)&ath, g_ath);  cudaGetSymbolAddress((void**)&atl, g_atl);
    cudaGetSymbolAddress((void**)&fh,  g_fh);   cudaGetSymbolAddress((void**)&fl,  g_fl);
    cudaGetSymbolAddress((void**)&qh,  g_qh);   cudaGetSymbolAddress((void**)&ql_, g_ql);
    cudaGetSymbolAddress((void**)&kh,  g_kh);   cudaGetSymbolAddress((void**)&klo, g_klo);
    cudaGetSymbolAddress((void**)&ph,  g_ph);   cudaGetSymbolAddress((void**)&pl,  g_pl);
    cudaGetSymbolAddress((void**)&vth, g_vth);  cudaGetSymbolAddress((void**)&vtl, g_vtl);
    cudaGetSymbolAddress((void**)&wqh, g_WqTh); cudaGetSymbolAddress((void**)&wql, g_WqTl);
    cudaGetSymbolAddress((void**)&wkh, g_WkTh); cudaGetSymbolAddress((void**)&wkl, g_WkTl);
    cudaGetSymbolAddress((void**)&wvh, g_WvTh); cudaGetSymbolAddress((void**)&wvl, g_WvTl);
    cudaGetSymbolAddress((void**)&woh, g_WoTh); cudaGetSymbolAddress((void**)&wol, g_WoTl);
    cudaGetSymbolAddress((void**)&w1h, g_W1Th); cudaGetSymbolAddress((void**)&w1l, g_W1Tl);
    cudaGetSymbolAddress((void**)&w2h, g_W2Th); cudaGetSymbolAddress((void**)&w2l, g_W2Tl);

    cudaFuncSetAttribute(hmma_gemm<0,0,0>, cudaFuncAttributeMaxDynamicSharedMemorySize, HM_SMEM);
    cudaFuncSetAttribute(hmma_gemm<2,0,0>, cudaFuncAttributeMaxDynamicSharedMemorySize, HM_SMEM);
    cudaFuncSetAttribute(hmma_gemm<5,1,0>, cudaFuncAttributeMaxDynamicSharedMemorySize, HM_SMEM);
    cudaFuncSetAttribute(hmma_gemm<3,0,1>, cudaFuncAttributeMaxDynamicSharedMemorySize, HM_SMEM);
    cudaFuncSetAttribute(hmma_gemm<4,0,0>, cudaFuncAttributeMaxDynamicSharedMemorySize, HM_SMEM);

    // 0) weight splits (transposed to [N,K] TS)
    k_split_wT<<<dim3(Dm/128,  Dm/64,  1),256>>>(Wq, wqh, wql, Dm, Dm, Dm, 0, 0);
    k_split_wT<<<dim3(Dm/128,  Dm/64,  1),256>>>(Wk, wkh, wkl, Dm, Dm, Dm, 0, 0);
    k_split_wT<<<dim3(Dm/128,  Dm/64,  1),256>>>(Wv, wvh, wvl, Dm, Dm, Dm, 0, 0);
    k_split_wT<<<dim3(Dm/128,  Dm/64,  1),256>>>(Wo, woh, wol, Dm, Dm, Dm, 0, 0);
    k_split_wT<<<dim3(DFFd/128,Dm/64,  1),256>>>(W1, w1h, w1l, Dm, DFFd, DFFd, 0, 0);
    k_split_wT<<<dim3(Dm/128,  DFFd/64,1),256>>>(W2, w2h, w2l, DFFd, Dm, Dm, 0, 0);

    // 1) u0 = log(x); v1 = norm1(u0) -> u fp32 + vh/vl TS
    k_lognorm1<<<ROWS,256>>>(x, scale1, u, vh, vl);

    // 2) QKV projections (fp32 out; norms needed downstream)
    dim3 gQ(Dm/128, ROWS/128);
    hmma_gemm<0,0,0><<<gQ,256,HM_SMEM>>>(vh, vl, wqh, wql, q,  nullptr, 0,0, 0,0, Dm/64, Dm, 0, 0,0, 0, 0);
    hmma_gemm<0,0,0><<<gQ,256,HM_SMEM>>>(vh, vl, wkh, wkl, k,  nullptr, 0,0, 0,0, Dm/64, Dm, 0, 0,0, 0, 0);
    hmma_gemm<0,0,0><<<gQ,256,HM_SMEM>>>(vh, vl, wvh, wvl, vv, nullptr, 0,0, 0,0, Dm/64, Dm, 0, 0,0, 0, 0);

    // 3) lorentz lift -> TS hi/lo (128 dims) + rank-1 vectors
    k_qlkl<<<dim3(ROWS,Hh),128>>>(headK, q, k, qh, ql_, kh, klo, ax, bx);

    // 4) causal scores: probs = q@k^T + ax⊗bx (fp32, causal tiles only)
    hmma_gemm<5,1,0><<<dim3(Sq/128, Sq/128, BHn),256,HM_SMEM>>>(
        qh, ql_, kh, klo, probs, nullptr, 0,0, ax, bx, 2, Sq, 0, Sq/128, Sq/128, (long long)Sq*Sq, 0);

    // 5) causal softmax fused with bf16 split -> ph/pl TS
    k_softmax<<<BHn*Sq,256>>>(probs, ph, pl);

    // 6) V^T per-head split, then PV (k-limited) -> ath/atl TS directly
    k_split_wT<<<dim3(1, Sq/64, BHn),256>>>(vv, vth, vtl, Sq, DHd, Dm, 1, (long long)(Sq/64)*1024);
    hmma_gemm<3,0,1><<<dim3(1, Sq/128, BHn),256,HM_SMEM>>>(
        ph, pl, vth, vtl, nullptr, nullptr, ath, atl, 0,0, Sq/64, 0, Dm/64, Sq/128, 1, 0, 1);

    // 7) Wo projection + residual: u += attn@Wo
    hmma_gemm<2,0,0><<<gQ,256,HM_SMEM>>>(ath, atl, woh, wol, u, u, 0,0, 0,0, Dm/64, Dm, 0, 0,0, 0, 0);

    // 8) v2 = norm2(u1) -> vh/vl TS
    k_norm2<<<ROWS,256>>>(u, scale2, vh, vl);

    // 9) FFN up + exact gelu -> fh/fl TS directly
    hmma_gemm<4,0,0><<<dim3(DFFd/128, ROWS/128),256,HM_SMEM>>>(
        vh, vl, w1h, w1l, nullptr, nullptr, fh, fl, 0,0, Dm/64, 0, DFFd/64, 0,0, 0, 0);

    // 10) FFN down + residual: u += gelu@W2
    hmma_gemm<2,0,0><<<gQ,256,HM_SMEM>>>(fh, fl, w2h, w2l, u, u, 0,0, 0,0, DFFd/64, Dm, 0, 0,0, 0, 0);

    // 11) out = exp_map(u2)
    k_expmap<<<ROWS,256>>>(u, out);
}

// round 7
// speedup vs baseline: 3.3866x; 1.0196x over previous
#include <cuda_runtime.h>
#include <cuda_bf16.h>
#include <math.h>
#include <stdint.h>

// Problem dims (fixed)
#define Bz   2
#define Sq   2048
#define Dm   2048
#define Hh   16
#define DHd  128
#define DFFd 8192
#define ROWS (Bz*Sq)       // 4096
#define BHn  (Bz*Hh)       // 32
#define EPSn 1e-6f

// ================= PTX helpers (baseline compute_103 features only) =================
__device__ __forceinline__ uint32_t smem_u32(const void* p){
    uint32_t r;
    asm("{ .reg .u64 t; cvta.to.shared.u64 t, %1; cvt.u32.u64 %0, t; }" : "=r"(r) : "l"(p));
    return r;
}
#define MB_INIT(addr,cnt) asm volatile("mbarrier.init.shared.b64 [%0], %1;"::"r"(addr),"r"(cnt):"memory")
#define MB_EXPECT_TX(addr,tx) asm volatile("mbarrier.arrive.expect_tx.shared.b64 _, [%0], %1;"::"r"(addr),"r"(tx):"memory")
#define MB_WAIT(addr, ph) do { \
    asm volatile("{\n\t.reg .pred P1;\n\tWL%=:\n\t" \
        "mbarrier.try_wait.parity.acquire.cta.shared::cta.b64 P1, [%0], %1, 0x989680;\n\t" \
        "@P1 bra.uni WD%=;\n\tbra.uni WL%=;\n\tWD%=:\n\t}" \
        :: "r"(addr), "r"(ph) : "memory"); } while(0)
#define BULK16K(dst, src, mb) asm volatile( \
    "cp.async.bulk.shared::cta.global.mbarrier::complete_tx::bytes [%0], [%1], %2, [%3];" \
    :: "r"(dst), "l"(src), "r"(16384), "r"(mb) : "memory")
#define LDSM4(r0,r1,r2,r3,addr) asm volatile( \
    "ldmatrix.sync.aligned.m8n8.x4.shared.b16 {%0,%1,%2,%3},[%4];" \
    : "=r"(r0),"=r"(r1),"=r"(r2),"=r"(r3) : "r"(addr))
#define MMA16816(c, a, b0, b1) asm volatile( \
    "mma.sync.aligned.m16n8k16.row.col.f32.bf16.bf16.f32 " \
    "{%0,%1,%2,%3},{%4,%5,%6,%7},{%8,%9},{%0,%1,%2,%3};" \
    : "+f"((c)[0]),"+f"((c)[1]),"+f"((c)[2]),"+f"((c)[3]) \
    : "r"((a)[0]),"r"((a)[1]),"r"((a)[2]),"r"((a)[3]), "r"(b0),"r"(b1))
#define SWZ(o) ((o) ^ (((o)>>3)&0x70))

// ================= scratch (device globals) =================
__device__ float g_u   [(size_t)ROWS*Dm];
__device__ float g_q   [(size_t)ROWS*Dm];
__device__ float g_k   [(size_t)ROWS*Dm];
__device__ float g_vv  [(size_t)ROWS*Dm];
__device__ float g_probs[(size_t)BHn*Sq*Sq];    // raw scores (fp32, causal tiles only)
__device__ float g_ax  [(size_t)BHn*Sq];        // -gsc*x0_q
__device__ float g_bx  [(size_t)BHn*Sq];        // x0_k

// bf16 hi/lo tiled-swizzled (TS) operands, uint4 granules (= elems/8).
// TS: [R,C] as tiles 128r x 64c bf16; tile (tr,kc) at granule (tr*(C/64)+kc)*1024,
// interior: granule index = SWZ(r*128 + g*16)>>4  (g = col/8).
__device__ uint4 g_vh  [(size_t)ROWS*Dm/8],   g_vl  [(size_t)ROWS*Dm/8];
__device__ uint4 g_ath [(size_t)ROWS*Dm/8],   g_atl [(size_t)ROWS*Dm/8];
__device__ uint4 g_fh  [(size_t)ROWS*DFFd/8], g_fl  [(size_t)ROWS*DFFd/8];
__device__ uint4 g_qh  [(size_t)BHn*Sq*DHd/8], g_ql [(size_t)BHn*Sq*DHd/8];
__device__ uint4 g_kh  [(size_t)BHn*Sq*DHd/8], g_klo[(size_t)BHn*Sq*DHd/8];
__device__ uint4 g_ph  [(size_t)BHn*Sq*Sq/8],  g_pl [(size_t)BHn*Sq*Sq/8];
__device__ uint4 g_vth [(size_t)BHn*DHd*Sq/8], g_vtl[(size_t)BHn*DHd*Sq/8];
__device__ uint4 g_WqTh[(size_t)Dm*Dm/8], g_WqTl[(size_t)Dm*Dm/8];
__device__ uint4 g_WkTh[(size_t)Dm*Dm/8], g_WkTl[(size_t)Dm*Dm/8];
__device__ uint4 g_WvTh[(size_t)Dm*Dm/8], g_WvTl[(size_t)Dm*Dm/8];
__device__ uint4 g_WoTh[(size_t)Dm*Dm/8], g_WoTl[(size_t)Dm*Dm/8];
__device__ uint4 g_W1Th[(size_t)Dm*DFFd/8], g_W1Tl[(size_t)Dm*DFFd/8];
__device__ uint4 g_W2Th[(size_t)Dm*DFFd/8], g_W2Tl[(size_t)Dm*DFFd/8];

union Pack8 { __nv_bfloat16 b[8]; uint4 v; };

// ================= reductions =================
__device__ __forceinline__ float warpSum(float v){
    #pragma unroll
    for (int o=16;o;o>>=1) v += __shfl_xor_sync(0xffffffffu, v, o);
    return v;
}
__device__ __forceinline__ float warpMax(float v){
    #pragma unroll
    for (int o=16;o;o>>=1) v = fmaxf(v, __shfl_xor_sync(0xffffffffu, v, o));
    return v;
}
__device__ __forceinline__ float blockSum(float v){
    __shared__ float sh[32];
    int lane = threadIdx.x & 31, w = threadIdx.x >> 5, nw = (blockDim.x + 31) >> 5;
    v = warpSum(v);
    __syncthreads();
    if (lane == 0) sh[w] = v;
    __syncthreads();
    float r = (lane < nw) ? sh[lane] : 0.f;
    return warpSum(r);
}
__device__ __forceinline__ float blockMax(float v){
    __shared__ float sh[32];
    int lane = threadIdx.x & 31, w = threadIdx.x >> 5, nw = (blockDim.x + 31) >> 5;
    v = warpMax(v);
    __syncthreads();
    if (lane == 0) sh[w] = v;
    __syncthreads();
    float r = (lane < nw) ? sh[lane] : -1e30f;
    return warpMax(r);
}

__device__ __forceinline__ void split_pack(const float* xs, Pack8& H, Pack8& L){
    #pragma unroll
    for (int j=0;j<8;j++){
        __nv_bfloat16 h = __float2bfloat16(xs[j]);
        H.b[j] = h;
        L.b[j] = __float2bfloat16(xs[j] - __bfloat162float(h));
    }
}

// ================= fused elementwise kernels =================
// NOTE: x rows have stride 2049 floats (+1 offset) -> NOT 16B aligned; load scalars.
__global__ void k_lognorm1(const float* __restrict__ x, const float* __restrict__ scale,
                           float* __restrict__ u, uint4* __restrict__ vh, uint4* __restrict__ vl){
    int row = blockIdx.x, t = threadIdx.x;
    const float* xr = x + (size_t)row*(Dm+1) + 1 + t*8;
    float xs[8];
    #pragma unroll
    for (int j=0;j<8;j++) xs[j] = xr[j];
    float ss = 0.f;
    #pragma unroll
    for (int j=0;j<8;j++) ss += xs[j]*xs[j];
    float n2 = blockSum(ss);
    float a  = sqrtf(n2);
    float f  = (a < 1e-6f) ? (1.f - a*a*(1.f/6.f)) : (asinhf(a)/fmaxf(a,1e-12f));
    float rms = sqrtf(f*f*n2*(1.f/(float)Dm) + EPSn);
    float inv = 1.f/rms;
    float4 S0 = *(const float4*)(scale + t*8), S1 = *(const float4*)(scale + t*8 + 4);
    float sc[8] = {S0.x,S0.y,S0.z,S0.w,S1.x,S1.y,S1.z,S1.w};
    float us[8], vs[8];
    #pragma unroll
    for (int j=0;j<8;j++){ us[j] = f*xs[j]; vs[j] = sc[j]*us[j]*inv; }
    float* ur = u + (size_t)row*Dm + t*8;
    *(float4*)ur     = make_float4(us[0],us[1],us[2],us[3]);
    *(float4*)(ur+4) = make_float4(us[4],us[5],us[6],us[7]);
    Pack8 H, L; split_pack(vs, H, L);
    uint32_t tr = row>>7, rl = row&127;
    int kc = t>>3, gg = t&7;
    size_t blk = (((size_t)tr*(Dm/64) + kc)<<10) + (SWZ((uint32_t)(rl*128 + gg*16))>>4);
    vh[blk] = H.v; vl[blk] = L.v;
}

__global__ void k_norm2(const float* __restrict__ u, const float* __restrict__ scale,
                        uint4* __restrict__ vh, uint4* __restrict__ vl){
    int row = blockIdx.x, t = threadIdx.x;
    const float* ur = u + (size_t)row*Dm + t*8;
    float4 A = *(const float4*)ur, B = *(const float4*)(ur+4);
    float xs[8] = {A.x,A.y,A.z,A.w,B.x,B.y,B.z,B.w};
    float ss = 0.f;
    #pragma unroll
    for (int j=0;j<8;j++) ss += xs[j]*xs[j];
    float n2 = blockSum(ss);
    float rms = sqrtf(n2*(1.f/(float)Dm) + EPSn);
    float inv = 1.f/rms;
    float4 S0 = *(const float4*)(scale + t*8), S1 = *(const float4*)(scale + t*8 + 4);
    float sc[8] = {S0.x,S0.y,S0.z,S0.w,S1.x,S1.y,S1.z,S1.w};
    float vs[8];
    #pragma unroll
    for (int j=0;j<8;j++) vs[j] = sc[j]*xs[j]*inv;
    Pack8 H, L; split_pack(vs, H, L);
    uint32_t tr = row>>7, rl = row&127;
    int kc = t>>3, gg = t&7;
    size_t blk = (((size_t)tr*(Dm/64) + kc)<<10) + (SWZ((uint32_t)(rl*128 + gg*16))>>4);
    vh[blk] = H.v; vl[blk] = L.v;
}

// per-head lorentz lift: q,k (fp32) -> TS hi/lo (128 dims) + rank-1 vectors ax,bx.
__global__ void k_qlkl(const float* __restrict__ headK,
                       const float* __restrict__ qsrc, const float* __restrict__ ksrc,
                       uint4* __restrict__ qh, uint4* __restrict__ ql,
                       uint4* __restrict__ kh, uint4* __restrict__ klo,
                       float* __restrict__ ax, float* __restrict__ bx){
    int bs = blockIdx.x, h = blockIdx.y, t = threadIdx.x;
    float qv = qsrc[(size_t)bs*Dm + h*DHd + t];
    float kv = ksrc[(size_t)bs*Dm + h*DHd + t];
    float n2q = blockSum(qv*qv);
    float n2k = blockSum(kv*kv);
    float Kh = headK[h]; float sK = sqrtf(-Kh);
    float aq = sK*sqrtf(n2q);
    float sincq = (aq<1e-6f)?(1.f+aq*aq*(1.f/6.f)):(sinhf(aq)/fmaxf(aq,1e-12f));
    float x0q = sqrtf(-1.f/Kh + sincq*sincq*n2q);
    float ak = sK*sqrtf(n2k);
    float sinck = (ak<1e-6f)?(1.f+ak*ak*(1.f/6.f)):(sinhf(ak)/fmaxf(ak,1e-12f));
    float x0k = sqrtf(-1.f/Kh + sinck*sinck*n2k);
    const float gsc = 0.1767766952966369f;    // 2/sqrt(128)
    __shared__ float sq[128], sk[128];
    sq[t] = gsc*sincq*qv;
    sk[t] = sinck*kv;
    int b = bs >> 11, s = bs & 2047;
    size_t R = ((size_t)(b*Hh + h)<<11) + s;
    if (t==0){ ax[R] = -gsc*x0q; bx[R] = x0k; }
    __syncthreads();
    uint32_t tr = (uint32_t)(R>>7), rl = (uint32_t)(R&127);
    int which = t>>4, g = t&15;
    if (which < 4){
        int kc = g>>3, gg = g&7;
        size_t blk = (((size_t)tr*2 + kc)<<10) + (SWZ(rl*128 + gg*16)>>4);
        const float* sv = (which<2) ? sq : sk;
        Pack8 p;
        #pragma unroll
        for (int j=0;j<8;j++){
            float xv = sv[g*8+j];
            __nv_bfloat16 hh = __float2bfloat16(xv);
            p.b[j] = (which&1) ? __float2bfloat16(xv - __bfloat162float(hh)) : hh;
        }
        uint4* dst = (which==0)?qh:(which==1)?ql:(which==2)?kh:klo;
        dst[blk] = p.v;
    }
}

// causal softmax fused with bf16 hi/lo split.
// Writes ph/pl through the end of the 256-row TILE PAIR (even tile boundary) so the
// 256-row PV GEMM never reads unwritten blocks; masked entries are exact zeros.
__global__ void k_softmax(const float* __restrict__ probs,
                          uint4* __restrict__ ph, uint4* __restrict__ pl){
    int row = blockIdx.x;
    int qi = row & 2047;
    const float* p = probs + (size_t)row*Sq;
    int t = threadIdx.x;
    int qt = qi >> 7;
    int lastg = ((qt|1)+1) << 4;      // granules through end of 256-pair
    bool act = t < lastg;
    float vals[8];
    float m = -1e30f;
    if (act){
        float4 A = *(const float4*)(p + t*8), B = *(const float4*)(p + t*8 + 4);
        vals[0]=A.x; vals[1]=A.y; vals[2]=A.z; vals[3]=A.w;
        vals[4]=B.x; vals[5]=B.y; vals[6]=B.z; vals[7]=B.w;
        #pragma unroll
        for (int j=0;j<8;j++){
            if (t*8+j > qi) vals[j] = -1e30f;
            m = fmaxf(m, vals[j]);
        }
    } else {
        #pragma unroll
        for (int j=0;j<8;j++) vals[j] = -1e30f;
    }
    m = blockMax(m);
    float s = 0.f;
    #pragma unroll
    for (int j=0;j<8;j++){
        float e = (vals[j] > -1e29f) ? expf(vals[j]-m) : 0.f;
        vals[j] = e; s += e;
    }
    s = blockSum(s);
    float inv = 1.f/s;
    if (act){
        float ps[8];
        #pragma unroll
        for (int j=0;j<8;j++) ps[j] = vals[j]*inv;
        Pack8 H, L; split_pack(ps, H, L);
        uint32_t tr = (uint32_t)row>>7, rl = (uint32_t)row&127;
        int kc = t>>3, gg = t&7;
        size_t blk = (((size_t)tr*(Sq/64) + kc)<<10) + (SWZ(rl*128 + gg*16)>>4);
        ph[blk] = H.v; pl[blk] = L.v;
    }
}

__global__ void k_expmap(const float* __restrict__ u, float* __restrict__ out){
    int row = blockIdx.x, tid = threadIdx.x;
    const float* ur = u + (size_t)row*Dm;
    float loc[8]; float s = 0.f;
    #pragma unroll
    for (int j=0;j<8;j++){ float t = ur[tid + j*256]; loc[j]=t; s += t*t; }
    float n2 = blockSum(s);
    float a = sqrtf(n2);
    float sinc = (a < 1e-6f) ? (1.f + a*a*(1.f/6.f)) : (sinhf(a)/fmaxf(a,1e-12f));
    float x0 = sqrtf(1.f + sinc*sinc*n2);
    float* o = out + (size_t)row*(Dm+1);
    if (tid==0) o[0] = x0;
    #pragma unroll
    for (int j=0;j<8;j++){ int d = tid + j*256; o[1+d] = sinc*loc[j]; }
}

// ================= weight / V-transpose split =================
__global__ void k_split_wT(const float* __restrict__ W, uint4* __restrict__ Hi,
                           uint4* __restrict__ Lo, int K, int N, int ld,
                           int hmode, long long outzG){
    __shared__ float s[64][129];
    int tr = blockIdx.x, kc = blockIdx.y, bz = blockIdx.z;
    int ntc = K >> 6;
    const float* Wb = W + (hmode ? ((long long)(bz>>4)*(long long)Sq*Dm + (long long)(bz&15)*DHd) : 0);
    Hi += (size_t)bz*outzG; Lo += (size_t)bz*outzG;
    int n0 = tr*128, k0 = kc*64;
    int col = threadIdx.x & 127, r0 = threadIdx.x >> 7;
    #pragma unroll
    for (int i=0;i<32;i++){
        int r = r0 + i*2;
        s[r][col] = Wb[(size_t)(k0+r)*ld + n0 + col];
    }
    __syncthreads();
    size_t blk = ((size_t)tr*ntc + kc)*1024;
    #pragma unroll
    for (int i=0;i<4;i++){
        int gid = threadIdx.x + i*256;
        int nl = gid >> 3, g = gid & 7;
        Pack8 uh, ul;
        #pragma unroll
        for (int j=0;j<8;j++){
            float x = s[g*8+j][nl];
            __nv_bfloat16 h = __float2bfloat16(x);
            uh.b[j] = h;
            ul.b[j] = __float2bfloat16(x - __bfloat162float(h));
        }
        uint32_t off = SWZ((uint32_t)(nl*128 + g*16)) >> 4;
        Hi[blk + off] = uh.v;
        Lo[blk + off] = ul.v;
    }
}

// ================= HMMA bf16x3 pipelined GEMM: 256(M) x 128(N) tile, 512 thr =================
// Stage (96KB): [Ah0 | Ah1 | Al0 | Al1 | Bh | Bl] x 16KB. 2-stage ring.
// EPI: 0 fp32 out; 2 fp32 += ADD; 3 TS hi/lo out; 4 gelu + TS hi/lo out; 5 fp32 + rank-1.
// CSKIP: causal pair skip (tnx > 2*tmy+1). KLIM: causal k-chunk limit 4*(tmy+1).
#define STAGE_B 98304
#define HM_SMEM (2*STAGE_B + 1024)

template<int EPI, int CSKIP, int KLIM>
__global__ void __launch_bounds__(512, 1)
hmma_gemm(const uint4* __restrict__ Ah, const uint4* __restrict__ Al,
          const uint4* __restrict__ Bh, const uint4* __restrict__ Bl,
          float* __restrict__ C, const float* __restrict__ ADD,
          uint4* __restrict__ OHi, uint4* __restrict__ OLo,
          const float* __restrict__ AX, const float* __restrict__ BX,
          int nk, int ldc, int ntc, int mtb, int ntb, long long sC, int cmode){
    extern __shared__ char dsm[];
    __shared__ __align__(8) unsigned long long s_mbar[2];
    int tnx = blockIdx.x, tmy = blockIdx.y, bz = blockIdx.z;
    if (CSKIP && tnx > 2*tmy+1) return;
    int nkc = nk;
    if (KLIM) nkc = min(nk, 4*(tmy+1));
    int atr0 = bz*mtb + 2*tmy;          // two A tile-rows: atr0, atr0+1
    int btr  = bz*ntb + tnx;

    uint32_t ab = (smem_u32(dsm) + 1023) & ~1023u;
    int tid = threadIdx.x, wid = tid >> 5, l = tid & 31;
    int wm = wid >> 2, wn = wid & 3;    // 4 x 4 warp grid; warp = 64 rows x 32 cols

    uint32_t mb[2];
    if (tid == 0){
        MB_INIT(smem_u32(&s_mbar[0]), 1);
        MB_INIT(smem_u32(&s_mbar[1]), 1);
    }
    mb[0] = smem_u32(&s_mbar[0]); mb[1] = smem_u32(&s_mbar[1]);
    __syncthreads();

    if (tid == 0){
        int pre = min(2, nkc);
        for (int c = 0; c < pre; c++){
            uint32_t base = ab + c*STAGE_B;
            MB_EXPECT_TX(mb[c], STAGE_B);
            BULK16K(base,         (const void*)(Ah + ((size_t)atr0*nk + c)*1024), mb[c]);
            BULK16K(base + 16384, (const void*)(Ah + ((size_t)(atr0+1)*nk + c)*1024), mb[c]);
            BULK16K(base + 32768, (const void*)(Al + ((size_t)atr0*nk + c)*1024), mb[c]);
            BULK16K(base + 49152, (const void*)(Al + ((size_t)(atr0+1)*nk + c)*1024), mb[c]);
            BULK16K(base + 65536, (const void*)(Bh + ((size_t)btr*nk + c)*1024), mb[c]);
            BULK16K(base + 81920, (const void*)(Bl + ((size_t)btr*nk + c)*1024), mb[c]);
        }
    }

    // per-lane ldmatrix row offsets (bytes within a 16KB block)
    int arow[4], brow[2];
    #pragma unroll
    for (int mt=0; mt<4; mt++)
        arow[mt] = ((wm&1)*64 + mt*16 + (l&7) + ((l>>3)&1)*8) * 128;
    #pragma unroll
    for (int p=0; p<2; p++)
        brow[p] = (wn*32 + p*16 + ((l>>4)&1)*8 + (l&7)) * 128;
    int akg = (l>>4)&1, bkg = (l>>3)&1, l7 = l&7;
    uint32_t ablk = (uint32_t)(wm>>1)*16384u;

    float acc[4][4][4];
    #pragma unroll
    for (int i=0;i<4;i++)
        #pragma unroll
        for (int j=0;j<4;j++)
            #pragma unroll
            for (int t=0;t<4;t++) acc[i][j][t] = 0.f;

    for (int c = 0; c < nkc; c++){
        int s = c & 1;
        MB_WAIT(mb[s], (c>>1)&1);
        uint32_t stg = ab + s*STAGE_B;
        uint32_t aHb = stg + ablk;              // Ah block for this warp
        uint32_t aLb = aHb + 32768;             // Al block
        uint32_t bHb = stg + 65536, bLb = stg + 81920;
        #pragma unroll
        for (int kk = 0; kk < 4; kk++){
            int kxA = ((kk*2 + akg) ^ l7) << 4;
            int kxB = ((kk*2 + bkg) ^ l7) << 4;
            uint32_t bhr[4][2], blr[4][2];
            #pragma unroll
            for (int p=0; p<2; p++){
                LDSM4(bhr[2*p][0],bhr[2*p][1],bhr[2*p+1][0],bhr[2*p+1][1], bHb + brow[p] + kxB);
                LDSM4(blr[2*p][0],blr[2*p][1],blr[2*p+1][0],blr[2*p+1][1], bLb + brow[p] + kxB);
            }
            #pragma unroll
            for (int mt=0; mt<4; mt++){
                uint32_t ahf[4], alf[4];
                LDSM4(ahf[0],ahf[1],ahf[2],ahf[3], aHb + arow[mt] + kxA);
                LDSM4(alf[0],alf[1],alf[2],alf[3], aLb + arow[mt] + kxA);
                #pragma unroll
                for (int nt=0; nt<4; nt++){
                    MMA16816(acc[mt][nt], ahf, bhr[nt][0], bhr[nt][1]);
                    MMA16816(acc[mt][nt], ahf, blr[nt][0], blr[nt][1]);
                    MMA16816(acc[mt][nt], alf, bhr[nt][0], bhr[nt][1]);
                }
            }
        }
        __syncthreads();
        if (tid == 0 && c + 2 < nkc){
            int cc = c + 2;
            uint32_t base = ab + s*STAGE_B;
            MB_EXPECT_TX(mb[s], STAGE_B);
            BULK16K(base,         (const void*)(Ah + ((size_t)atr0*nk + cc)*1024), mb[s]);
            BULK16K(base + 16384, (const void*)(Ah + ((size_t)(atr0+1)*nk + cc)*1024), mb[s]);
            BULK16K(base + 32768, (const void*)(Al + ((size_t)atr0*nk + cc)*1024), mb[s]);
            BULK16K(base + 49152, (const void*)(Al + ((size_t)(atr0+1)*nk + cc)*1024), mb[s]);
            BULK16K(base + 65536, (const void*)(Bh + ((size_t)btr*nk + cc)*1024), mb[s]);
            BULK16K(base + 81920, (const void*)(Bl + ((size_t)btr*nk + cc)*1024), mb[s]);
        }
    }

    // -------- epilogue --------
    if (EPI == 3 || EPI == 4){
        int otrBase, ocol0;
        if (cmode){ otrBase = (bz>>4)*(Sq/128) + tmy*2; ocol0 = (bz&15)*DHd + tnx*128; }
        else      { otrBase = tmy*2;                    ocol0 = tnx*128; }
        int otr = otrBase + (wm>>1);
        char* HiB = (char*)OHi;
        char* LoB = (char*)OLo;
        #pragma unroll
        for (int mt=0; mt<4; mt++){
            int rl = (wm&1)*64 + mt*16 + (l>>2);     // row within 128-tile
            uint32_t ro0 = (uint32_t)(rl*128), ro1 = (uint32_t)((rl+8)*128);
            #pragma unroll
            for (int nt=0; nt<4; nt++){
                int col = ocol0 + wn*32 + nt*8 + (l&3)*2;
                float v0 = acc[mt][nt][0], v1 = acc[mt][nt][1];
                float v2 = acc[mt][nt][2], v3 = acc[mt][nt][3];
                if (EPI == 4){
                    v0 = 0.5f*v0*(1.f + erff(v0*0.7071067811865475f));
                    v1 = 0.5f*v1*(1.f + erff(v1*0.7071067811865475f));
                    v2 = 0.5f*v2*(1.f + erff(v2*0.7071067811865475f));
                    v3 = 0.5f*v3*(1.f + erff(v3*0.7071067811865475f));
                }
                int kcn = col>>6, g = (col>>3)&7, w2 = (col&7)*2;
                size_t blkB = (((size_t)otr*ntc + kcn)<<14);
                uint32_t o0 = SWZ(ro0 + g*16) + w2;
                uint32_t o1 = SWZ(ro1 + g*16) + w2;
                __nv_bfloat16 h0 = __float2bfloat16(v0), h1 = __float2bfloat16(v1);
                __nv_bfloat16 h2 = __float2bfloat16(v2), h3 = __float2bfloat16(v3);
                __nv_bfloat16 l0 = __float2bfloat16(v0 - __bfloat162float(h0));
                __nv_bfloat16 l1 = __float2bfloat16(v1 - __bfloat162float(h1));
                __nv_bfloat16 l2 = __float2bfloat16(v2 - __bfloat162float(h2));
                __nv_bfloat16 l3 = __float2bfloat16(v3 - __bfloat162float(h3));
                *(uint32_t*)(HiB + blkB + o0) = (uint32_t)__bfloat16_as_ushort(h0) | ((uint32_t)__bfloat16_as_ushort(h1)<<16);
                *(uint32_t*)(LoB + blkB + o0) = (uint32_t)__bfloat16_as_ushort(l0) | ((uint32_t)__bfloat16_as_ushort(l1)<<16);
                *(uint32_t*)(HiB + blkB + o1) = (uint32_t)__bfloat16_as_ushort(h2) | ((uint32_t)__bfloat16_as_ushort(h3)<<16);
                *(uint32_t*)(LoB + blkB + o1) = (uint32_t)__bfloat16_as_ushort(l2) | ((uint32_t)__bfloat16_as_ushort(l3)<<16);
            }
        }
    } else {
        long long offC = cmode ? ((long long)(bz>>4)*(long long)Sq*Dm + (long long)(bz&15)*DHd)
                               : (long long)bz*sC;
        float* Cb = C + offC + (size_t)tmy*256*ldc + (size_t)tnx*128;
        const float* Ab = (EPI==2) ? (ADD + offC + (size_t)tmy*256*ldc + (size_t)tnx*128) : nullptr;
        const float* axp = (EPI==5) ? (AX + (size_t)bz*Sq + tmy*256) : nullptr;
        const float* bxp = (EPI==5) ? (BX + (size_t)bz*Sq + tnx*128) : nullptr;
        #pragma unroll
        for (int mt=0; mt<4; mt++){
            int r0 = wm*64 + mt*16 + (l>>2);
            float a0 = 0.f, a1 = 0.f;
            if (EPI==5){ a0 = axp[r0]; a1 = axp[r0+8]; }
            #pragma unroll
            for (int nt=0; nt<4; nt++){
                int cc = wn*32 + nt*8 + (l&3)*2;
                float v0 = acc[mt][nt][0], v1 = acc[mt][nt][1];
                float v2 = acc[mt][nt][2], v3 = acc[mt][nt][3];
                if (EPI==5){
                    float b0 = bxp[cc], b1 = bxp[cc+1];
                    v0 += a0*b0; v1 += a0*b1; v2 += a1*b0; v3 += a1*b1;
                }
                if (EPI==2){
                    float2 x0 = *(const float2*)&Ab[(size_t)r0*ldc + cc];
                    float2 x1 = *(const float2*)&Ab[(size_t)(r0+8)*ldc + cc];
                    v0 += x0.x; v1 += x0.y; v2 += x1.x; v3 += x1.y;
                }
                *(float2*)&Cb[(size_t)r0*ldc + cc]     = make_float2(v0, v1);
                *(float2*)&Cb[(size_t)(r0+8)*ldc + cc] = make_float2(v2, v3);
            }
        }
    }
}

// ================= launch =================
extern "C" void kernel_launch(void* const* d_in, const int* in_sizes, int n_in,
                              void* d_out, int out_size){
    const float* x      = (const float*)d_in[0];
    const float* scale1 = (const float*)d_in[2];
    const float* scale2 = (const float*)d_in[3];
    const float* Wq     = (const float*)d_in[4];
    const float* Wk     = (const float*)d_in[5];
    const float* Wv     = (const float*)d_in[6];
    const float* Wo     = (const float*)d_in[7];
    const float* headK  = (const float*)d_in[8];
    const float* W1     = (const float*)d_in[9];
    const float* W2     = (const float*)d_in[10];
    float* out = (float*)d_out;

    float *u,*q,*k,*vv,*probs,*ax,*bx;
    cudaGetSymbolAddress((void**)&u,    g_u);
    cudaGetSymbolAddress((void**)&q,    g_q);
    cudaGetSymbolAddress((void**)&k,    g_k);
    cudaGetSymbolAddress((void**)&vv,   g_vv);
    cudaGetSymbolAddress((void**)&probs,g_probs);
    cudaGetSymbolAddress((void**)&ax,   g_ax);
    cudaGetSymbolAddress((void**)&bx,   g_bx);

    uint4 *vh,*vl,*ath,*atl,*fh,*fl,*qh,*ql_,*kh,*klo,*ph,*pl,*vth,*vtl;
    uint4 *wqh,*wql,*wkh,*wkl,*wvh,*wvl,*woh,*wol,*w1h,*w1l,*w2h,*w2l;
    cudaGetSymbolAddress((void**)&vh,  g_vh);   cudaGetSymbolAddress((void**)&vl,  g_vl);
    cudaGetSymbolAddress((void**)&ath, g_ath);  cudaGetSymbolAddress((void**)&atl, g_atl);
    cudaGetSymbolAddress((void**)&fh,  g_fh);   cudaGetSymbolAddress((void**)&fl,  g_fl);
    cudaGetSymbolAddress((void**)&qh,  g_qh);   cudaGetSymbolAddress((void**)&ql_, g_ql);
    cudaGetSymbolAddress((void**)&kh,  g_kh);   cudaGetSymbolAddress((void**)&klo, g_klo);
    cudaGetSymbolAddress((void**)&ph,  g_ph);   cudaGetSymbolAddress((void**)&pl,  g_pl);
    cudaGetSymbolAddress((void**)&vth, g_vth);  cudaGetSymbolAddress((void**)&vtl, g_vtl);
    cudaGetSymbolAddress((void**)&wqh, g_WqTh); cudaGetSymbolAddress((void**)&wql, g_WqTl);
    cudaGetSymbolAddress((void**)&wkh, g_WkTh); cudaGetSymbolAddress((void**)&wkl, g_WkTl);
    cudaGetSymbolAddress((void**)&wvh, g_WvTh); cudaGetSymbolAddress((void**)&wvl, g_WvTl);
    cudaGetSymbolAddress((void**)&woh, g_WoTh); cudaGetSymbolAddress((void**)&wol, g_WoTl);
    cudaGetSymbolAddress((void**)&w1h, g_W1Th); cudaGetSymbolAddress((void**)&w1l, g_W1Tl);
    cudaGetSymbolAddress((void**)&w2h, g_W2Th); cudaGetSymbolAddress((void**)&w2l, g_W2Tl);

    cudaFuncSetAttribute(hmma_gemm<0,0,0>, cudaFuncAttributeMaxDynamicSharedMemorySize, HM_SMEM);
    cudaFuncSetAttribute(hmma_gemm<2,0,0>, cudaFuncAttributeMaxDynamicSharedMemorySize, HM_SMEM);
    cudaFuncSetAttribute(hmma_gemm<5,1,0>, cudaFuncAttributeMaxDynamicSharedMemorySize, HM_SMEM);
    cudaFuncSetAttribute(hmma_gemm<3,0,1>, cudaFuncAttributeMaxDynamicSharedMemorySize, HM_SMEM);
    cudaFuncSetAttribute(hmma_gemm<4,0,0>, cudaFuncAttributeMaxDynamicSharedMemorySize, HM_SMEM);

    // 0) weight splits (transposed to [N,K] TS)
    k_split_wT<<<dim3(Dm/128,  Dm/64,  1),256>>>(Wq, wqh, wql, Dm, Dm, Dm, 0, 0);
    k_split_wT<<<dim3(Dm/128,  Dm/64,  1),256>>>(Wk, wkh, wkl, Dm, Dm, Dm, 0, 0);
    k_split_wT<<<dim3(Dm/128,  Dm/64,  1),256>>>(Wv, wvh, wvl, Dm, Dm, Dm, 0, 0);
    k_split_wT<<<dim3(Dm/128,  Dm/64,  1),256>>>(Wo, woh, wol, Dm, Dm, Dm, 0, 0);
    k_split_wT<<<dim3(DFFd/128,Dm/64,  1),256>>>(W1, w1h, w1l, Dm, DFFd, DFFd, 0, 0);
    k_split_wT<<<dim3(Dm/128,  DFFd/64,1),256>>>(W2, w2h, w2l, DFFd, Dm, Dm, 0, 0);

    // 1) u0 = log(x); v1 = norm1(u0) -> u fp32 + vh/vl TS
    k_lognorm1<<<ROWS,256>>>(x, scale1, u, vh, vl);

    // 2) QKV projections (M-tiles of 256)
    dim3 gQ(Dm/128, ROWS/256);
    hmma_gemm<0,0,0><<<gQ,512,HM_SMEM>>>(vh, vl, wqh, wql, q,  nullptr, 0,0, 0,0, Dm/64, Dm, 0, ROWS/128, Dm/128, 0, 0);
    hmma_gemm<0,0,0><<<gQ,512,HM_SMEM>>>(vh, vl, wkh, wkl, k,  nullptr, 0,0, 0,0, Dm/64, Dm, 0, ROWS/128, Dm/128, 0, 0);
    hmma_gemm<0,0,0><<<gQ,512,HM_SMEM>>>(vh, vl, wvh, wvl, vv, nullptr, 0,0, 0,0, Dm/64, Dm, 0, ROWS/128, Dm/128, 0, 0);

    // 3) lorentz lift -> TS hi/lo (128 dims) + rank-1 vectors
    k_qlkl<<<dim3(ROWS,Hh),128>>>(headK, q, k, qh, ql_, kh, klo, ax, bx);

    // 4) causal scores: probs = q@k^T + ax⊗bx (pair-tile causal skip)
    hmma_gemm<5,1,0><<<dim3(Sq/128, Sq/256, BHn),512,HM_SMEM>>>(
        qh, ql_, kh, klo, probs, nullptr, 0,0, ax, bx, 2, Sq, 0, Sq/128, Sq/128, (long long)Sq*Sq, 0);

    // 5) causal softmax fused with bf16 split -> ph/pl TS (pair-boundary zero fill)
    k_softmax<<<BHn*Sq,256>>>(probs, ph, pl);

    // 6) V^T per-head split, then PV (k-limited) -> ath/atl TS directly
    k_split_wT<<<dim3(1, Sq/64, BHn),256>>>(vv, vth, vtl, Sq, DHd, Dm, 1, (long long)(Sq/64)*1024);
    hmma_gemm<3,0,1><<<dim3(1, Sq/256, BHn),512,HM_SMEM>>>(
        ph, pl, vth, vtl, nullptr, nullptr, ath, atl, 0,0, Sq/64, 0, Dm/64, Sq/128, 1, 0, 1);

    // 7) Wo projection + residual: u += attn@Wo
    hmma_gemm<2,0,0><<<gQ,512,HM_SMEM>>>(ath, atl, woh, wol, u, u, 0,0, 0,0, Dm/64, Dm, 0, ROWS/128, Dm/128, 0, 0);

    // 8) v2 = norm2(u1) -> vh/vl TS
    k_norm2<<<ROWS,256>>>(u, scale2, vh, vl);

    // 9) FFN up + exact gelu -> fh/fl TS directly
    hmma_gemm<4,0,0><<<dim3(DFFd/128, ROWS/256),512,HM_SMEM>>>(
        vh, vl, w1h, w1l, nullptr, nullptr, fh, fl, 0,0, Dm/64, 0, DFFd/64, ROWS/128, DFFd/128, 0, 0);

    // 10) FFN down + residual: u += gelu@W2
    hmma_gemm<2,0,0><<<gQ,512,HM_SMEM>>>(fh, fl, w2h, w2l, u, u, 0,0, 0,0, DFFd/64, Dm, 0, ROWS/128, Dm/128, 0, 0);

    // 11) out = exp_map(u2)
    k_expmap<<<ROWS,256>>>(u, out);
}

// round 8
// speedup vs baseline: 3.3999x; 1.0039x over previous
#include <cuda_runtime.h>
#include <cuda_bf16.h>
#include <math.h>
#include <stdint.h>

// Problem dims (fixed)
#define Bz   2
#define Sq   2048
#define Dm   2048
#define Hh   16
#define DHd  128
#define DFFd 8192
#define ROWS (Bz*Sq)       // 4096
#define BHn  (Bz*Hh)       // 32
#define EPSn 1e-6f

// ================= PTX helpers (baseline compute_103 features only) =================
__device__ __forceinline__ uint32_t smem_u32(const void* p){
    uint32_t r;
    asm("{ .reg .u64 t; cvta.to.shared.u64 t, %1; cvt.u32.u64 %0, t; }" : "=r"(r) : "l"(p));
    return r;
}
#define MB_INIT(addr,cnt) asm volatile("mbarrier.init.shared.b64 [%0], %1;"::"r"(addr),"r"(cnt):"memory")
#define MB_EXPECT_TX(addr,tx) asm volatile("mbarrier.arrive.expect_tx.shared.b64 _, [%0], %1;"::"r"(addr),"r"(tx):"memory")
#define MB_ARRIVE(addr) asm volatile("mbarrier.arrive.shared.b64 _, [%0];"::"r"(addr):"memory")
#define MB_WAIT(addr, ph) do { \
    asm volatile("{\n\t.reg .pred P1;\n\tWL%=:\n\t" \
        "mbarrier.try_wait.parity.acquire.cta.shared::cta.b64 P1, [%0], %1, 0x989680;\n\t" \
        "@P1 bra.uni WD%=;\n\tbra.uni WL%=;\n\tWD%=:\n\t}" \
        :: "r"(addr), "r"(ph) : "memory"); } while(0)
#define BULK16K(dst, src, mb) asm volatile( \
    "cp.async.bulk.shared::cta.global.mbarrier::complete_tx::bytes [%0], [%1], %2, [%3];" \
    :: "r"(dst), "l"(src), "r"(16384), "r"(mb) : "memory")
#define LDSM4(r0,r1,r2,r3,addr) asm volatile( \
    "ldmatrix.sync.aligned.m8n8.x4.shared.b16 {%0,%1,%2,%3},[%4];" \
    : "=r"(r0),"=r"(r1),"=r"(r2),"=r"(r3) : "r"(addr))
#define MMA16816(c, a, b0, b1) asm volatile( \
    "mma.sync.aligned.m16n8k16.row.col.f32.bf16.bf16.f32 " \
    "{%0,%1,%2,%3},{%4,%5,%6,%7},{%8,%9},{%0,%1,%2,%3};" \
    : "+f"((c)[0]),"+f"((c)[1]),"+f"((c)[2]),"+f"((c)[3]) \
    : "r"((a)[0]),"r"((a)[1]),"r"((a)[2]),"r"((a)[3]), "r"(b0),"r"(b1))
#define SWZ(o) ((o) ^ (((o)>>3)&0x70))

// ================= scratch (device globals) =================
__device__ float g_u   [(size_t)ROWS*Dm];
__device__ float g_q   [(size_t)ROWS*Dm];
__device__ float g_k   [(size_t)ROWS*Dm];
__device__ float g_vv  [(size_t)ROWS*Dm];
__device__ float g_probs[(size_t)BHn*Sq*Sq];    // raw scores (fp32, causal tiles only)
__device__ float g_ax  [(size_t)BHn*Sq];        // -gsc*x0_q
__device__ float g_bx  [(size_t)BHn*Sq];        // x0_k

// bf16 hi/lo tiled-swizzled (TS) operands, uint4 granules (= elems/8).
// TS: [R,C] as tiles 128r x 64c bf16; tile (tr,kc) at granule (tr*(C/64)+kc)*1024,
// interior: granule index = SWZ(r*128 + g*16)>>4  (g = col/8).
__device__ uint4 g_vh  [(size_t)ROWS*Dm/8],   g_vl  [(size_t)ROWS*Dm/8];
__device__ uint4 g_ath [(size_t)ROWS*Dm/8],   g_atl [(size_t)ROWS*Dm/8];
__device__ uint4 g_fh  [(size_t)ROWS*DFFd/8], g_fl  [(size_t)ROWS*DFFd/8];
__device__ uint4 g_qh  [(size_t)BHn*Sq*DHd/8], g_ql [(size_t)BHn*Sq*DHd/8];
__device__ uint4 g_kh  [(size_t)BHn*Sq*DHd/8], g_klo[(size_t)BHn*Sq*DHd/8];
__device__ uint4 g_ph  [(size_t)BHn*Sq*Sq/8],  g_pl [(size_t)BHn*Sq*Sq/8];
__device__ uint4 g_vth [(size_t)BHn*DHd*Sq/8], g_vtl[(size_t)BHn*DHd*Sq/8];
__device__ uint4 g_WqTh[(size_t)Dm*Dm/8], g_WqTl[(size_t)Dm*Dm/8];
__device__ uint4 g_WkTh[(size_t)Dm*Dm/8], g_WkTl[(size_t)Dm*Dm/8];
__device__ uint4 g_WvTh[(size_t)Dm*Dm/8], g_WvTl[(size_t)Dm*Dm/8];
__device__ uint4 g_WoTh[(size_t)Dm*Dm/8], g_WoTl[(size_t)Dm*Dm/8];
__device__ uint4 g_W1Th[(size_t)Dm*DFFd/8], g_W1Tl[(size_t)Dm*DFFd/8];
__device__ uint4 g_W2Th[(size_t)Dm*DFFd/8], g_W2Tl[(size_t)Dm*DFFd/8];

union Pack8 { __nv_bfloat16 b[8]; uint4 v; };

// ================= reductions =================
__device__ __forceinline__ float warpSum(float v){
    #pragma unroll
    for (int o=16;o;o>>=1) v += __shfl_xor_sync(0xffffffffu, v, o);
    return v;
}
__device__ __forceinline__ float warpMax(float v){
    #pragma unroll
    for (int o=16;o;o>>=1) v = fmaxf(v, __shfl_xor_sync(0xffffffffu, v, o));
    return v;
}
__device__ __forceinline__ float blockSum(float v){
    __shared__ float sh[32];
    int lane = threadIdx.x & 31, w = threadIdx.x >> 5, nw = (blockDim.x + 31) >> 5;
    v = warpSum(v);
    __syncthreads();
    if (lane == 0) sh[w] = v;
    __syncthreads();
    float r = (lane < nw) ? sh[lane] : 0.f;
    return warpSum(r);
}
__device__ __forceinline__ float blockMax(float v){
    __shared__ float sh[32];
    int lane = threadIdx.x & 31, w = threadIdx.x >> 5, nw = (blockDim.x + 31) >> 5;
    v = warpMax(v);
    __syncthreads();
    if (lane == 0) sh[w] = v;
    __syncthreads();
    float r = (lane < nw) ? sh[lane] : -1e30f;
    return warpMax(r);
}

__device__ __forceinline__ void split_pack(const float* xs, Pack8& H, Pack8& L){
    #pragma unroll
    for (int j=0;j<8;j++){
        __nv_bfloat16 h = __float2bfloat16(xs[j]);
        H.b[j] = h;
        L.b[j] = __float2bfloat16(xs[j] - __bfloat162float(h));
    }
}

// ================= fused elementwise kernels =================
// NOTE: x rows have stride 2049 floats (+1 offset) -> NOT 16B aligned; load scalars.
__global__ void k_lognorm1(const float* __restrict__ x, const float* __restrict__ scale,
                           float* __restrict__ u, uint4* __restrict__ vh, uint4* __restrict__ vl){
    int row = blockIdx.x, t = threadIdx.x;
    const float* xr = x + (size_t)row*(Dm+1) + 1 + t*8;
    float xs[8];
    #pragma unroll
    for (int j=0;j<8;j++) xs[j] = xr[j];
    float ss = 0.f;
    #pragma unroll
    for (int j=0;j<8;j++) ss += xs[j]*xs[j];
    float n2 = blockSum(ss);
    float a  = sqrtf(n2);
    float f  = (a < 1e-6f) ? (1.f - a*a*(1.f/6.f)) : (asinhf(a)/fmaxf(a,1e-12f));
    float rms = sqrtf(f*f*n2*(1.f/(float)Dm) + EPSn);
    float inv = 1.f/rms;
    float4 S0 = *(const float4*)(scale + t*8), S1 = *(const float4*)(scale + t*8 + 4);
    float sc[8] = {S0.x,S0.y,S0.z,S0.w,S1.x,S1.y,S1.z,S1.w};
    float us[8], vs[8];
    #pragma unroll
    for (int j=0;j<8;j++){ us[j] = f*xs[j]; vs[j] = sc[j]*us[j]*inv; }
    float* ur = u + (size_t)row*Dm + t*8;
    *(float4*)ur     = make_float4(us[0],us[1],us[2],us[3]);
    *(float4*)(ur+4) = make_float4(us[4],us[5],us[6],us[7]);
    Pack8 H, L; split_pack(vs, H, L);
    uint32_t tr = row>>7, rl = row&127;
    int kc = t>>3, gg = t&7;
    size_t blk = (((size_t)tr*(Dm/64) + kc)<<10) + (SWZ((uint32_t)(rl*128 + gg*16))>>4);
    vh[blk] = H.v; vl[blk] = L.v;
}

__global__ void k_norm2(const float* __restrict__ u, const float* __restrict__ scale,
                        uint4* __restrict__ vh, uint4* __restrict__ vl){
    int row = blockIdx.x, t = threadIdx.x;
    const float* ur = u + (size_t)row*Dm + t*8;
    float4 A = *(const float4*)ur, B = *(const float4*)(ur+4);
    float xs[8] = {A.x,A.y,A.z,A.w,B.x,B.y,B.z,B.w};
    float ss = 0.f;
    #pragma unroll
    for (int j=0;j<8;j++) ss += xs[j]*xs[j];
    float n2 = blockSum(ss);
    float rms = sqrtf(n2*(1.f/(float)Dm) + EPSn);
    float inv = 1.f/rms;
    float4 S0 = *(const float4*)(scale + t*8), S1 = *(const float4*)(scale + t*8 + 4);
    float sc[8] = {S0.x,S0.y,S0.z,S0.w,S1.x,S1.y,S1.z,S1.w};
    float vs[8];
    #pragma unroll
    for (int j=0;j<8;j++) vs[j] = sc[j]*xs[j]*inv;
    Pack8 H, L; split_pack(vs, H, L);
    uint32_t tr = row>>7, rl = row&127;
    int kc = t>>3, gg = t&7;
    size_t blk = (((size_t)tr*(Dm/64) + kc)<<10) + (SWZ((uint32_t)(rl*128 + gg*16))>>4);
    vh[blk] = H.v; vl[blk] = L.v;
}

// per-head lorentz lift: q,k (fp32) -> TS hi/lo (128 dims) + rank-1 vectors ax,bx.
__global__ void k_qlkl(const float* __restrict__ headK,
                       const float* __restrict__ qsrc, const float* __restrict__ ksrc,
                       uint4* __restrict__ qh, uint4* __restrict__ ql,
                       uint4* __restrict__ kh, uint4* __restrict__ klo,
                       float* __restrict__ ax, float* __restrict__ bx){
    int bs = blockIdx.x, h = blockIdx.y, t = threadIdx.x;
    float qv = qsrc[(size_t)bs*Dm + h*DHd + t];
    float kv = ksrc[(size_t)bs*Dm + h*DHd + t];
    float n2q = blockSum(qv*qv);
    float n2k = blockSum(kv*kv);
    float Kh = headK[h]; float sK = sqrtf(-Kh);
    float aq = sK*sqrtf(n2q);
    float sincq = (aq<1e-6f)?(1.f+aq*aq*(1.f/6.f)):(sinhf(aq)/fmaxf(aq,1e-12f));
    float x0q = sqrtf(-1.f/Kh + sincq*sincq*n2q);
    float ak = sK*sqrtf(n2k);
    float sinck = (ak<1e-6f)?(1.f+ak*ak*(1.f/6.f)):(sinhf(ak)/fmaxf(ak,1e-12f));
    float x0k = sqrtf(-1.f/Kh + sinck*sinck*n2k);
    const float gsc = 0.1767766952966369f;    // 2/sqrt(128)
    __shared__ float sq[128], sk[128];
    sq[t] = gsc*sincq*qv;
    sk[t] = sinck*kv;
    int b = bs >> 11, s = bs & 2047;
    size_t R = ((size_t)(b*Hh + h)<<11) + s;
    if (t==0){ ax[R] = -gsc*x0q; bx[R] = x0k; }
    __syncthreads();
    uint32_t tr = (uint32_t)(R>>7), rl = (uint32_t)(R&127);
    int which = t>>4, g = t&15;
    if (which < 4){
        int kc = g>>3, gg = g&7;
        size_t blk = (((size_t)tr*2 + kc)<<10) + (SWZ(rl*128 + gg*16)>>4);
        const float* sv = (which<2) ? sq : sk;
        Pack8 p;
        #pragma unroll
        for (int j=0;j<8;j++){
            float xv = sv[g*8+j];
            __nv_bfloat16 hh = __float2bfloat16(xv);
            p.b[j] = (which&1) ? __float2bfloat16(xv - __bfloat162float(hh)) : hh;
        }
        uint4* dst = (which==0)?qh:(which==1)?ql:(which==2)?kh:klo;
        dst[blk] = p.v;
    }
}

// causal softmax fused with bf16 hi/lo split.
// Writes ph/pl through the end of the 256-row TILE PAIR so the 256-row PV GEMM
// never reads unwritten blocks; masked entries are exact zeros.
__global__ void k_softmax(const float* __restrict__ probs,
                          uint4* __restrict__ ph, uint4* __restrict__ pl){
    int row = blockIdx.x;
    int qi = row & 2047;
    const float* p = probs + (size_t)row*Sq;
    int t = threadIdx.x;
    int qt = qi >> 7;
    int lastg = ((qt|1)+1) << 4;      // granules through end of 256-pair
    bool act = t < lastg;
    float vals[8];
    float m = -1e30f;
    if (act){
        float4 A = *(const float4*)(p + t*8), B = *(const float4*)(p + t*8 + 4);
        vals[0]=A.x; vals[1]=A.y; vals[2]=A.z; vals[3]=A.w;
        vals[4]=B.x; vals[5]=B.y; vals[6]=B.z; vals[7]=B.w;
        #pragma unroll
        for (int j=0;j<8;j++){
            if (t*8+j > qi) vals[j] = -1e30f;
            m = fmaxf(m, vals[j]);
        }
    } else {
        #pragma unroll
        for (int j=0;j<8;j++) vals[j] = -1e30f;
    }
    m = blockMax(m);
    float s = 0.f;
    #pragma unroll
    for (int j=0;j<8;j++){
        float e = (vals[j] > -1e29f) ? expf(vals[j]-m) : 0.f;
        vals[j] = e; s += e;
    }
    s = blockSum(s);
    float inv = 1.f/s;
    if (act){
        float ps[8];
        #pragma unroll
        for (int j=0;j<8;j++) ps[j] = vals[j]*inv;
        Pack8 H, L; split_pack(ps, H, L);
        uint32_t tr = (uint32_t)row>>7, rl = (uint32_t)row&127;
        int kc = t>>3, gg = t&7;
        size_t blk = (((size_t)tr*(Sq/64) + kc)<<10) + (SWZ(rl*128 + gg*16)>>4);
        ph[blk] = H.v; pl[blk] = L.v;
    }
}

__global__ void k_expmap(const float* __restrict__ u, float* __restrict__ out){
    int row = blockIdx.x, tid = threadIdx.x;
    const float* ur = u + (size_t)row*Dm;
    float loc[8]; float s = 0.f;
    #pragma unroll
    for (int j=0;j<8;j++){ float t = ur[tid + j*256]; loc[j]=t; s += t*t; }
    float n2 = blockSum(s);
    float a = sqrtf(n2);
    float sinc = (a < 1e-6f) ? (1.f + a*a*(1.f/6.f)) : (sinhf(a)/fmaxf(a,1e-12f));
    float x0 = sqrtf(1.f + sinc*sinc*n2);
    float* o = out + (size_t)row*(Dm+1);
    if (tid==0) o[0] = x0;
    #pragma unroll
    for (int j=0;j<8;j++){ int d = tid + j*256; o[1+d] = sinc*loc[j]; }
}

// ================= weight / V-transpose split =================
__global__ void k_split_wT(const float* __restrict__ W, uint4* __restrict__ Hi,
                           uint4* __restrict__ Lo, int K, int N, int ld,
                           int hmode, long long outzG){
    __shared__ float s[64][129];
    int tr = blockIdx.x, kc = blockIdx.y, bz = blockIdx.z;
    int ntc = K >> 6;
    const float* Wb = W + (hmode ? ((long long)(bz>>4)*(long long)Sq*Dm + (long long)(bz&15)*DHd) : 0);
    Hi += (size_t)bz*outzG; Lo += (size_t)bz*outzG;
    int n0 = tr*128, k0 = kc*64;
    int col = threadIdx.x & 127, r0 = threadIdx.x >> 7;
    #pragma unroll
    for (int i=0;i<32;i++){
        int r = r0 + i*2;
        s[r][col] = Wb[(size_t)(k0+r)*ld + n0 + col];
    }
    __syncthreads();
    size_t blk = ((size_t)tr*ntc + kc)*1024;
    #pragma unroll
    for (int i=0;i<4;i++){
        int gid = threadIdx.x + i*256;
        int nl = gid >> 3, g = gid & 7;
        Pack8 uh, ul;
        #pragma unroll
        for (int j=0;j<8;j++){
            float x = s[g*8+j][nl];
            __nv_bfloat16 h = __float2bfloat16(x);
            uh.b[j] = h;
            ul.b[j] = __float2bfloat16(x - __bfloat162float(h));
        }
        uint32_t off = SWZ((uint32_t)(nl*128 + g*16)) >> 4;
        Hi[blk + off] = uh.v;
        Lo[blk + off] = ul.v;
    }
}

// ================= HMMA bf16x3 pipelined GEMM: 256(M) x 128(N) tile, 512 thr =================
// Stage (96KB): [Ah0 | Ah1 | Al0 | Al1 | Bh | Bl] x 16KB. 2-stage ring.
// Pipeline: per-stage FULL (tx) + EMPTY (16 warp arrivals) mbarriers; no per-chunk
// __syncthreads — only the producer (tid0) waits for stage emptiness.
// EPI: 0 fp32 out; 2 fp32 += ADD; 3 TS hi/lo out; 4 gelu + TS hi/lo out; 5 fp32 + rank-1.
// CSKIP: causal pair skip (tnx > 2*tmy+1). KLIM: causal k-chunk limit 4*(tmy+1).
#define STAGE_B 98304
#define HM_SMEM (2*STAGE_B + 1024)

template<int EPI, int CSKIP, int KLIM>
__global__ void __launch_bounds__(512, 1)
hmma_gemm(const uint4* __restrict__ Ah, const uint4* __restrict__ Al,
          const uint4* __restrict__ Bh, const uint4* __restrict__ Bl,
          float* __restrict__ C, const float* __restrict__ ADD,
          uint4* __restrict__ OHi, uint4* __restrict__ OLo,
          const float* __restrict__ AX, const float* __restrict__ BX,
          int nk, int ldc, int ntc, int mtb, int ntb, long long sC, int cmode){
    extern __shared__ char dsm[];
    __shared__ __align__(8) unsigned long long s_mbar[4];   // full0, full1, emp0, emp1
    int tnx = blockIdx.x, tmy = blockIdx.y, bz = blockIdx.z;
    if (CSKIP && tnx > 2*tmy+1) return;
    int nkc = nk;
    if (KLIM) nkc = min(nk, 4*(tmy+1));
    int atr0 = bz*mtb + 2*tmy;          // two A tile-rows: atr0, atr0+1
    int btr  = bz*ntb + tnx;

    uint32_t ab = (smem_u32(dsm) + 1023) & ~1023u;
    int tid = threadIdx.x, wid = tid >> 5, l = tid & 31;
    int wm = wid >> 2, wn = wid & 3;    // 4 x 4 warp grid; warp = 64 rows x 32 cols

    uint32_t mb[2], me[2];
    if (tid == 0){
        MB_INIT(smem_u32(&s_mbar[0]), 1);
        MB_INIT(smem_u32(&s_mbar[1]), 1);
        MB_INIT(smem_u32(&s_mbar[2]), 16);
        MB_INIT(smem_u32(&s_mbar[3]), 16);
    }
    mb[0] = smem_u32(&s_mbar[0]); mb[1] = smem_u32(&s_mbar[1]);
    me[0] = smem_u32(&s_mbar[2]); me[1] = smem_u32(&s_mbar[3]);
    __syncthreads();

    if (tid == 0){
        int pre = min(2, nkc);
        for (int c = 0; c < pre; c++){
            uint32_t base = ab + c*STAGE_B;
            MB_EXPECT_TX(mb[c], STAGE_B);
            BULK16K(base,         (const void*)(Ah + ((size_t)atr0*nk + c)*1024), mb[c]);
            BULK16K(base + 16384, (const void*)(Ah + ((size_t)(atr0+1)*nk + c)*1024), mb[c]);
            BULK16K(base + 32768, (const void*)(Al + ((size_t)atr0*nk + c)*1024), mb[c]);
            BULK16K(base + 49152, (const void*)(Al + ((size_t)(atr0+1)*nk + c)*1024), mb[c]);
            BULK16K(base + 65536, (const void*)(Bh + ((size_t)btr*nk + c)*1024), mb[c]);
            BULK16K(base + 81920, (const void*)(Bl + ((size_t)btr*nk + c)*1024), mb[c]);
        }
    }

    // per-lane ldmatrix row offsets (bytes within a 16KB block)
    int arow[4], brow[2];
    #pragma unroll
    for (int mt=0; mt<4; mt++)
        arow[mt] = ((wm&1)*64 + mt*16 + (l&7) + ((l>>3)&1)*8) * 128;
    #pragma unroll
    for (int p=0; p<2; p++)
        brow[p] = (wn*32 + p*16 + ((l>>4)&1)*8 + (l&7)) * 128;
    int akg = (l>>4)&1, bkg = (l>>3)&1, l7 = l&7;
    uint32_t ablk = (uint32_t)(wm>>1)*16384u;

    float acc[4][4][4];
    #pragma unroll
    for (int i=0;i<4;i++)
        #pragma unroll
        for (int j=0;j<4;j++)
            #pragma unroll
            for (int t=0;t<4;t++) acc[i][j][t] = 0.f;

    for (int c = 0; c < nkc; c++){
        int s = c & 1;
        int ph = (c>>1)&1;
        MB_WAIT(mb[s], ph);
        uint32_t stg = ab + s*STAGE_B;
        uint32_t aHb = stg + ablk;              // Ah block for this warp
        uint32_t aLb = aHb + 32768;             // Al block
        uint32_t bHb = stg + 65536, bLb = stg + 81920;
        #pragma unroll
        for (int kk = 0; kk < 4; kk++){
            int kxA = ((kk*2 + akg) ^ l7) << 4;
            int kxB = ((kk*2 + bkg) ^ l7) << 4;
            uint32_t bhr[4][2], blr[4][2];
            #pragma unroll
            for (int p=0; p<2; p++){
                LDSM4(bhr[2*p][0],bhr[2*p][1],bhr[2*p+1][0],bhr[2*p+1][1], bHb + brow[p] + kxB);
                LDSM4(blr[2*p][0],blr[2*p][1],blr[2*p+1][0],blr[2*p+1][1], bLb + brow[p] + kxB);
            }
            #pragma unroll
            for (int mt=0; mt<4; mt++){
                uint32_t ahf[4], alf[4];
                LDSM4(ahf[0],ahf[1],ahf[2],ahf[3], aHb + arow[mt] + kxA);
                LDSM4(alf[0],alf[1],alf[2],alf[3], aLb + arow[mt] + kxA);
                #pragma unroll
                for (int nt=0; nt<4; nt++){
                    MMA16816(acc[mt][nt], ahf, bhr[nt][0], bhr[nt][1]);
                    MMA16816(acc[mt][nt], ahf, blr[nt][0], blr[nt][1]);
                    MMA16816(acc[mt][nt], alf, bhr[nt][0], bhr[nt][1]);
                }
            }
        }
        // this warp is done reading stage s
        if (l == 0) MB_ARRIVE(me[s]);
        // producer: wait all 16 warps done with stage s, then refill it for chunk c+2
        if (tid == 0 && c + 2 < nkc){
            MB_WAIT(me[s], ph);
            int cc = c + 2;
            uint32_t base = ab + s*STAGE_B;
            MB_EXPECT_TX(mb[s], STAGE_B);
            BULK16K(base,         (const void*)(Ah + ((size_t)atr0*nk + cc)*1024), mb[s]);
            BULK16K(base + 16384, (const void*)(Ah + ((size_t)(atr0+1)*nk + cc)*1024), mb[s]);
            BULK16K(base + 32768, (const void*)(Al + ((size_t)atr0*nk + cc)*1024), mb[s]);
            BULK16K(base + 49152, (const void*)(Al + ((size_t)(atr0+1)*nk + cc)*1024), mb[s]);
            BULK16K(base + 65536, (const void*)(Bh + ((size_t)btr*nk + cc)*1024), mb[s]);
            BULK16K(base + 81920, (const void*)(Bl + ((size_t)btr*nk + cc)*1024), mb[s]);
        }
    }

    // -------- epilogue --------
    if (EPI == 3 || EPI == 4){
        int otrBase, ocol0;
        if (cmode){ otrBase = (bz>>4)*(Sq/128) + tmy*2; ocol0 = (bz&15)*DHd + tnx*128; }
        else      { otrBase = tmy*2;                    ocol0 = tnx*128; }
        int otr = otrBase + (wm>>1);
        char* HiB = (char*)OHi;
        char* LoB = (char*)OLo;
        #pragma unroll
        for (int mt=0; mt<4; mt++){
            int rl = (wm&1)*64 + mt*16 + (l>>2);     // row within 128-tile
            uint32_t ro0 = (uint32_t)(rl*128), ro1 = (uint32_t)((rl+8)*128);
            #pragma unroll
            for (int nt=0; nt<4; nt++){
                int col = ocol0 + wn*32 + nt*8 + (l&3)*2;
                float v0 = acc[mt][nt][0], v1 = acc[mt][nt][1];
                float v2 = acc[mt][nt][2], v3 = acc[mt][nt][3];
                if (EPI == 4){
                    v0 = 0.5f*v0*(1.f + erff(v0*0.7071067811865475f));
                    v1 = 0.5f*v1*(1.f + erff(v1*0.7071067811865475f));
                    v2 = 0.5f*v2*(1.f + erff(v2*0.7071067811865475f));
                    v3 = 0.5f*v3*(1.f + erff(v3*0.7071067811865475f));
                }
                int kcn = col>>6, g = (col>>3)&7, w2 = (col&7)*2;
                size_t blkB = (((size_t)otr*ntc + kcn)<<14);
                uint32_t o0 = SWZ(ro0 + g*16) + w2;
                uint32_t o1 = SWZ(ro1 + g*16) + w2;
                __nv_bfloat16 h0 = __float2bfloat16(v0), h1 = __float2bfloat16(v1);
                __nv_bfloat16 h2 = __float2bfloat16(v2), h3 = __float2bfloat16(v3);
                __nv_bfloat16 l0 = __float2bfloat16(v0 - __bfloat162float(h0));
                __nv_bfloat16 l1 = __float2bfloat16(v1 - __bfloat162float(h1));
                __nv_bfloat16 l2 = __float2bfloat16(v2 - __bfloat162float(h2));
                __nv_bfloat16 l3 = __float2bfloat16(v3 - __bfloat162float(h3));
                *(uint32_t*)(HiB + blkB + o0) = (uint32_t)__bfloat16_as_ushort(h0) | ((uint32_t)__bfloat16_as_ushort(h1)<<16);
                *(uint32_t*)(LoB + blkB + o0) = (uint32_t)__bfloat16_as_ushort(l0) | ((uint32_t)__bfloat16_as_ushort(l1)<<16);
                *(uint32_t*)(HiB + blkB + o1) = (uint32_t)__bfloat16_as_ushort(h2) | ((uint32_t)__bfloat16_as_ushort(h3)<<16);
                *(uint32_t*)(LoB + blkB + o1) = (uint32_t)__bfloat16_as_ushort(l2) | ((uint32_t)__bfloat16_as_ushort(l3)<<16);
            }
        }
    } else {
        long long offC = cmode ? ((long long)(bz>>4)*(long long)Sq*Dm + (long long)(bz&15)*DHd)
                               : (long long)bz*sC;
        float* Cb = C + offC + (size_t)tmy*256*ldc + (size_t)tnx*128;
        const float* Ab = (EPI==2) ? (ADD + offC + (size_t)tmy*256*ldc + (size_t)tnx*128) : nullptr;
        const float* axp = (EPI==5) ? (AX + (size_t)bz*Sq + tmy*256) : nullptr;
        const float* bxp = (EPI==5) ? (BX + (size_t)bz*Sq + tnx*128) : nullptr;
        #pragma unroll
        for (int mt=0; mt<4; mt++){
            int r0 = wm*64 + mt*16 + (l>>2);
            float a0 = 0.f, a1 = 0.f;
            if (EPI==5){ a0 = axp[r0]; a1 = axp[r0+8]; }
            #pragma unroll
            for (int nt=0; nt<4; nt++){
                int cc = wn*32 + nt*8 + (l&3)*2;
                float v0 = acc[mt][nt][0], v1 = acc[mt][nt][1];
                float v2 = acc[mt][nt][2], v3 = acc[mt][nt][3];
                if (EPI==5){
                    float b0 = bxp[cc], b1 = bxp[cc+1];
                    v0 += a0*b0; v1 += a0*b1; v2 += a1*b0; v3 += a1*b1;
                }
                if (EPI==2){
                    float2 x0 = *(const float2*)&Ab[(size_t)r0*ldc + cc];
                    float2 x1 = *(const float2*)&Ab[(size_t)(r0+8)*ldc + cc];
                    v0 += x0.x; v1 += x0.y; v2 += x1.x; v3 += x1.y;
                }
                *(float2*)&Cb[(size_t)r0*ldc + cc]     = make_float2(v0, v1);
                *(float2*)&Cb[(size_t)(r0+8)*ldc + cc] = make_float2(v2, v3);
            }
        }
    }
}

// ================= launch =================
extern "C" void kernel_launch(void* const* d_in, const int* in_sizes, int n_in,
                              void* d_out, int out_size){
    const float* x      = (const float*)d_in[0];
    const float* scale1 = (const float*)d_in[2];
    const float* scale2 = (const float*)d_in[3];
    const float* Wq     = (const float*)d_in[4];
    const float* Wk     = (const float*)d_in[5];
    const float* Wv     = (const float*)d_in[6];
    const float* Wo     = (const float*)d_in[7];
    const float* headK  = (const float*)d_in[8];
    const float* W1     = (const float*)d_in[9];
    const float* W2     = (const float*)d_in[10];
    float* out = (float*)d_out;

    float *u,*q,*k,*vv,*probs,*ax,*bx;
    cudaGetSymbolAddress((void**)&u,    g_u);
    cudaGetSymbolAddress((void**)&q,    g_q);
    cudaGetSymbolAddress((void**)&k,    g_k);
    cudaGetSymbolAddress((void**)&vv,   g_vv);
    cudaGetSymbolAddress((void**)&probs,g_probs);
    cudaGetSymbolAddress((void**)&ax,   g_ax);
    cudaGetSymbolAddress((void**)&bx,   g_bx);

    uint4 *vh,*vl,*ath,*atl,*fh,*fl,*qh,*ql_,*kh,*klo,*ph,*pl,*vth,*vtl;
    uint4 *wqh,*wql,*wkh,*wkl,*wvh,*wvl,*woh,*wol,*w1h,*w1l,*w2h,*w2l;
    cudaGetSymbolAddress((void**)&vh,  g_vh);   cudaGetSymbolAddress((void**)&vl,  g_vl);
    cudaGetSymbolAddress((void**)&ath, g_ath);  cudaGetSymbolAddress((void**)&atl, g_atl);
    cudaGetSymbolAddress((void**)&fh,  g_fh);   cudaGetSymbolAddress((void**)&fl,  g_fl);
    cudaGetSymbolAddress((void**)&qh,  g_qh);   cudaGetSymbolAddress((void**)&ql_, g_ql);
    cudaGetSymbolAddress((void**)&kh,  g_kh);   cudaGetSymbolAddress((void**)&klo, g_klo);
    cudaGetSymbolAddress((void**)&ph,  g_ph);   cudaGetSymbolAddress((void**)&pl,  g_pl);
    cudaGetSymbolAddress((void**)&vth, g_vth);  cudaGetSymbolAddress((void**)&vtl, g_vtl);
    cudaGetSymbolAddress((void**)&wqh, g_WqTh); cudaGetSymbolAddress((void**)&wql, g_WqTl);
    cudaGetSymbolAddress((void**)&wkh, g_WkTh); cudaGetSymbolAddress((void**)&wkl, g_WkTl);
    cudaGetSymbolAddress((void**)&wvh, g_WvTh); cudaGetSymbolAddress((void**)&wvl, g_WvTl);
    cudaGetSymbolAddress((void**)&woh, g_WoTh); cudaGetSymbolAddress((void**)&wol, g_WoTl);
    cudaGetSymbolAddress((void**)&w1h, g_W1Th); cudaGetSymbolAddress((void**)&w1l, g_W1Tl);
    cudaGetSymbolAddress((void**)&w2h, g_W2Th); cudaGetSymbolAddress((void**)&w2l, g_W2Tl);

    cudaFuncSetAttribute(hmma_gemm<0,0,0>, cudaFuncAttributeMaxDynamicSharedMemorySize, HM_SMEM);
    cudaFuncSetAttribute(hmma_gemm<2,0,0>, cudaFuncAttributeMaxDynamicSharedMemorySize, HM_SMEM);
    cudaFuncSetAttribute(hmma_gemm<5,1,0>, cudaFuncAttributeMaxDynamicSharedMemorySize, HM_SMEM);
    cudaFuncSetAttribute(hmma_gemm<3,0,1>, cudaFuncAttributeMaxDynamicSharedMemorySize, HM_SMEM);
    cudaFuncSetAttribute(hmma_gemm<4,0,0>, cudaFuncAttributeMaxDynamicSharedMemorySize, HM_SMEM);

    // 0) weight splits (transposed to [N,K] TS)
    k_split_wT<<<dim3(Dm/128,  Dm/64,  1),256>>>(Wq, wqh, wql, Dm, Dm, Dm, 0, 0);
    k_split_wT<<<dim3(Dm/128,  Dm/64,  1),256>>>(Wk, wkh, wkl, Dm, Dm, Dm, 0, 0);
    k_split_wT<<<dim3(Dm/128,  Dm/64,  1),256>>>(Wv, wvh, wvl, Dm, Dm, Dm, 0, 0);
    k_split_wT<<<dim3(Dm/128,  Dm/64,  1),256>>>(Wo, woh, wol, Dm, Dm, Dm, 0, 0);
    k_split_wT<<<dim3(DFFd/128,Dm/64,  1),256>>>(W1, w1h, w1l, Dm, DFFd, DFFd, 0, 0);
    k_split_wT<<<dim3(Dm/128,  DFFd/64,1),256>>>(W2, w2h, w2l, DFFd, Dm, Dm, 0, 0);

    // 1) u0 = log(x); v1 = norm1(u0) -> u fp32 + vh/vl TS
    k_lognorm1<<<ROWS,256>>>(x, scale1, u, vh, vl);

    // 2) QKV projections (M-tiles of 256)
    dim3 gQ(Dm/128, ROWS/256);
    hmma_gemm<0,0,0><<<gQ,512,HM_SMEM>>>(vh, vl, wqh, wql, q,  nullptr, 0,0, 0,0, Dm/64, Dm, 0, ROWS/128, Dm/128, 0, 0);
    hmma_gemm<0,0,0><<<gQ,512,HM_SMEM>>>(vh, vl, wkh, wkl, k,  nullptr, 0,0, 0,0, Dm/64, Dm, 0, ROWS/128, Dm/128, 0, 0);
    hmma_gemm<0,0,0><<<gQ,512,HM_SMEM>>>(vh, vl, wvh, wvl, vv, nullptr, 0,0, 0,0, Dm/64, Dm, 0, ROWS/128, Dm/128, 0, 0);

    // 3) lorentz lift -> TS hi/lo (128 dims) + rank-1 vectors
    k_qlkl<<<dim3(ROWS,Hh),128>>>(headK, q, k, qh, ql_, kh, klo, ax, bx);

    // 4) causal scores: probs = q@k^T + ax⊗bx (pair-tile causal skip)
    hmma_gemm<5,1,0><<<dim3(Sq/128, Sq/256, BHn),512,HM_SMEM>>>(
        qh, ql_, kh, klo, probs, nullptr, 0,0, ax, bx, 2, Sq, 0, Sq/128, Sq/128, (long long)Sq*Sq, 0);

    // 5) causal softmax fused with bf16 split -> ph/pl TS (pair-boundary zero fill)
    k_softmax<<<BHn*Sq,256>>>(probs, ph, pl);

    // 6) V^T per-head split, then PV (k-limited) -> ath/atl TS directly
    k_split_wT<<<dim3(1, Sq/64, BHn),256>>>(vv, vth, vtl, Sq, DHd, Dm, 1, (long long)(Sq/64)*1024);
    hmma_gemm<3,0,1><<<dim3(1, Sq/256, BHn),512,HM_SMEM>>>(
        ph, pl, vth, vtl, nullptr, nullptr, ath, atl, 0,0, Sq/64, 0, Dm/64, Sq/128, 1, 0, 1);

    // 7) Wo projection + residual: u += attn@Wo
    hmma_gemm<2,0,0><<<gQ,512,HM_SMEM>>>(ath, atl, woh, wol, u, u, 0,0, 0,0, Dm/64, Dm, 0, ROWS/128, Dm/128, 0, 0);

    // 8) v2 = norm2(u1) -> vh/vl TS
    k_norm2<<<ROWS,256>>>(u, scale2, vh, vl);

    // 9) FFN up + exact gelu -> fh/fl TS directly
    hmma_gemm<4,0,0><<<dim3(DFFd/128, ROWS/256),512,HM_SMEM>>>(
        vh, vl, w1h, w1l, nullptr, nullptr, fh, fl, 0,0, Dm/64, 0, DFFd/64, ROWS/128, DFFd/128, 0, 0);

    // 10) FFN down + residual: u += gelu@W2
    hmma_gemm<2,0,0><<<gQ,512,HM_SMEM>>>(fh, fl, w2h, w2l, u, u, 0,0, 0,0, DFFd/64, Dm, 0, ROWS/128, Dm/128, 0, 0);

    // 11) out = exp_map(u2)
    k_expmap<<<ROWS,256>>>(u, out);
}

// round 9
// speedup vs baseline: 3.4019x; 1.0006x over previous
#include <cuda_runtime.h>
#include <cuda_bf16.h>
#include <math.h>
#include <stdint.h>

// Problem dims (fixed)
#define Bz   2
#define Sq   2048
#define Dm   2048
#define Hh   16
#define DHd  128
#define DFFd 8192
#define ROWS (Bz*Sq)       // 4096
#define BHn  (Bz*Hh)       // 32
#define EPSn 1e-6f

// ================= PTX helpers (baseline compute_103 features only) =================
__device__ __forceinline__ uint32_t smem_u32(const void* p){
    uint32_t r;
    asm("{ .reg .u64 t; cvta.to.shared.u64 t, %1; cvt.u32.u64 %0, t; }" : "=r"(r) : "l"(p));
    return r;
}
#define MB_INIT(addr,cnt) asm volatile("mbarrier.init.shared.b64 [%0], %1;"::"r"(addr),"r"(cnt):"memory")
#define MB_EXPECT_TX(addr,tx) asm volatile("mbarrier.arrive.expect_tx.shared.b64 _, [%0], %1;"::"r"(addr),"r"(tx):"memory")
#define MB_ARRIVE(addr) asm volatile("mbarrier.arrive.shared.b64 _, [%0];"::"r"(addr):"memory")
#define MB_WAIT(addr, ph) do { \
    asm volatile("{\n\t.reg .pred P1;\n\tWL%=:\n\t" \
        "mbarrier.try_wait.parity.acquire.cta.shared::cta.b64 P1, [%0], %1, 0x989680;\n\t" \
        "@P1 bra.uni WD%=;\n\tbra.uni WL%=;\n\tWD%=:\n\t}" \
        :: "r"(addr), "r"(ph) : "memory"); } while(0)
#define BULK16K(dst, src, mb) asm volatile( \
    "cp.async.bulk.shared::cta.global.mbarrier::complete_tx::bytes [%0], [%1], %2, [%3];" \
    :: "r"(dst), "l"(src), "r"(16384), "r"(mb) : "memory")
#define LDSM4(r0,r1,r2,r3,addr) asm volatile( \
    "ldmatrix.sync.aligned.m8n8.x4.shared.b16 {%0,%1,%2,%3},[%4];" \
    : "=r"(r0),"=r"(r1),"=r"(r2),"=r"(r3) : "r"(addr))
#define MMA16816(c, a, b0, b1) asm volatile( \
    "mma.sync.aligned.m16n8k16.row.col.f32.bf16.bf16.f32 " \
    "{%0,%1,%2,%3},{%4,%5,%6,%7},{%8,%9},{%0,%1,%2,%3};" \
    : "+f"((c)[0]),"+f"((c)[1]),"+f"((c)[2]),"+f"((c)[3]) \
    : "r"((a)[0]),"r"((a)[1]),"r"((a)[2]),"r"((a)[3]), "r"(b0),"r"(b1))
#define SWZ(o) ((o) ^ (((o)>>3)&0x70))

// ================= scratch (device globals) =================
__device__ float g_u   [(size_t)ROWS*Dm];
__device__ float g_q   [(size_t)ROWS*Dm];
__device__ float g_k   [(size_t)ROWS*Dm];
__device__ float g_vv  [(size_t)ROWS*Dm];
__device__ float g_probs[(size_t)BHn*Sq*Sq];    // raw scores (fp32, causal tiles only)
__device__ float g_ax  [(size_t)BHn*Sq];        // -gsc*x0_q
__device__ float g_bx  [(size_t)BHn*Sq];        // x0_k

// bf16 hi/lo tiled-swizzled (TS) operands, uint4 granules (= elems/8).
// TS: [R,C] as tiles 128r x 64c bf16; tile (tr,kc) at granule (tr*(C/64)+kc)*1024,
// interior: granule index = SWZ(r*128 + g*16)>>4  (g = col/8).
__device__ uint4 g_vh  [(size_t)ROWS*Dm/8],   g_vl  [(size_t)ROWS*Dm/8];
__device__ uint4 g_ath [(size_t)ROWS*Dm/8],   g_atl [(size_t)ROWS*Dm/8];
__device__ uint4 g_fh  [(size_t)ROWS*DFFd/8], g_fl  [(size_t)ROWS*DFFd/8];
__device__ uint4 g_qh  [(size_t)BHn*Sq*DHd/8], g_ql [(size_t)BHn*Sq*DHd/8];
__device__ uint4 g_kh  [(size_t)BHn*Sq*DHd/8], g_klo[(size_t)BHn*Sq*DHd/8];
__device__ uint4 g_ph  [(size_t)BHn*Sq*Sq/8],  g_pl [(size_t)BHn*Sq*Sq/8];
__device__ uint4 g_vth [(size_t)BHn*DHd*Sq/8], g_vtl[(size_t)BHn*DHd*Sq/8];
__device__ uint4 g_WqTh[(size_t)Dm*Dm/8], g_WqTl[(size_t)Dm*Dm/8];
__device__ uint4 g_WkTh[(size_t)Dm*Dm/8], g_WkTl[(size_t)Dm*Dm/8];
__device__ uint4 g_WvTh[(size_t)Dm*Dm/8], g_WvTl[(size_t)Dm*Dm/8];
__device__ uint4 g_WoTh[(size_t)Dm*Dm/8], g_WoTl[(size_t)Dm*Dm/8];
__device__ uint4 g_W1Th[(size_t)Dm*DFFd/8], g_W1Tl[(size_t)Dm*DFFd/8];
__device__ uint4 g_W2Th[(size_t)Dm*DFFd/8], g_W2Tl[(size_t)Dm*DFFd/8];

union Pack8 { __nv_bfloat16 b[8]; uint4 v; };

// ================= reductions =================
__device__ __forceinline__ float warpSum(float v){
    #pragma unroll
    for (int o=16;o;o>>=1) v += __shfl_xor_sync(0xffffffffu, v, o);
    return v;
}
__device__ __forceinline__ float warpMax(float v){
    #pragma unroll
    for (int o=16;o;o>>=1) v = fmaxf(v, __shfl_xor_sync(0xffffffffu, v, o));
    return v;
}
__device__ __forceinline__ float blockSum(float v){
    __shared__ float sh[32];
    int lane = threadIdx.x & 31, w = threadIdx.x >> 5, nw = (blockDim.x + 31) >> 5;
    v = warpSum(v);
    __syncthreads();
    if (lane == 0) sh[w] = v;
    __syncthreads();
    float r = (lane < nw) ? sh[lane] : 0.f;
    return warpSum(r);
}
__device__ __forceinline__ float blockMax(float v){
    __shared__ float sh[32];
    int lane = threadIdx.x & 31, w = threadIdx.x >> 5, nw = (blockDim.x + 31) >> 5;
    v = warpMax(v);
    __syncthreads();
    if (lane == 0) sh[w] = v;
    __syncthreads();
    float r = (lane < nw) ? sh[lane] : -1e30f;
    return warpMax(r);
}

__device__ __forceinline__ void split_pack(const float* xs, Pack8& H, Pack8& L){
    #pragma unroll
    for (int j=0;j<8;j++){
        __nv_bfloat16 h = __float2bfloat16(xs[j]);
        H.b[j] = h;
        L.b[j] = __float2bfloat16(xs[j] - __bfloat162float(h));
    }
}

// ================= fused elementwise kernels =================
// NOTE: x rows have stride 2049 floats (+1 offset) -> NOT 16B aligned; load scalars.
__global__ void k_lognorm1(const float* __restrict__ x, const float* __restrict__ scale,
                           float* __restrict__ u, uint4* __restrict__ vh, uint4* __restrict__ vl){
    int row = blockIdx.x, t = threadIdx.x;
    const float* xr = x + (size_t)row*(Dm+1) + 1 + t*8;
    float xs[8];
    #pragma unroll
    for (int j=0;j<8;j++) xs[j] = xr[j];
    float ss = 0.f;
    #pragma unroll
    for (int j=0;j<8;j++) ss += xs[j]*xs[j];
    float n2 = blockSum(ss);
    float a  = sqrtf(n2);
    float f  = (a < 1e-6f) ? (1.f - a*a*(1.f/6.f)) : (asinhf(a)/fmaxf(a,1e-12f));
    float rms = sqrtf(f*f*n2*(1.f/(float)Dm) + EPSn);
    float inv = 1.f/rms;
    float4 S0 = *(const float4*)(scale + t*8), S1 = *(const float4*)(scale + t*8 + 4);
    float sc[8] = {S0.x,S0.y,S0.z,S0.w,S1.x,S1.y,S1.z,S1.w};
    float us[8], vs[8];
    #pragma unroll
    for (int j=0;j<8;j++){ us[j] = f*xs[j]; vs[j] = sc[j]*us[j]*inv; }
    float* ur = u + (size_t)row*Dm + t*8;
    *(float4*)ur     = make_float4(us[0],us[1],us[2],us[3]);
    *(float4*)(ur+4) = make_float4(us[4],us[5],us[6],us[7]);
    Pack8 H, L; split_pack(vs, H, L);
    uint32_t tr = row>>7, rl = row&127;
    int kc = t>>3, gg = t&7;
    size_t blk = (((size_t)tr*(Dm/64) + kc)<<10) + (SWZ((uint32_t)(rl*128 + gg*16))>>4);
    vh[blk] = H.v; vl[blk] = L.v;
}

__global__ void k_norm2(const float* __restrict__ u, const float* __restrict__ scale,
                        uint4* __restrict__ vh, uint4* __restrict__ vl){
    int row = blockIdx.x, t = threadIdx.x;
    const float* ur = u + (size_t)row*Dm + t*8;
    float4 A = *(const float4*)ur, B = *(const float4*)(ur+4);
    float xs[8] = {A.x,A.y,A.z,A.w,B.x,B.y,B.z,B.w};
    float ss = 0.f;
    #pragma unroll
    for (int j=0;j<8;j++) ss += xs[j]*xs[j];
    float n2 = blockSum(ss);
    float rms = sqrtf(n2*(1.f/(float)Dm) + EPSn);
    float inv = 1.f/rms;
    float4 S0 = *(const float4*)(scale + t*8), S1 = *(const float4*)(scale + t*8 + 4);
    float sc[8] = {S0.x,S0.y,S0.z,S0.w,S1.x,S1.y,S1.z,S1.w};
    float vs[8];
    #pragma unroll
    for (int j=0;j<8;j++) vs[j] = sc[j]*xs[j]*inv;
    Pack8 H, L; split_pack(vs, H, L);
    uint32_t tr = row>>7, rl = row&127;
    int kc = t>>3, gg = t&7;
    size_t blk = (((size_t)tr*(Dm/64) + kc)<<10) + (SWZ((uint32_t)(rl*128 + gg*16))>>4);
    vh[blk] = H.v; vl[blk] = L.v;
}

// per-head lorentz lift: q,k (fp32) -> TS hi/lo (128 dims) + rank-1 vectors ax,bx.
__global__ void k_qlkl(const float* __restrict__ headK,
                       const float* __restrict__ qsrc, const float* __restrict__ ksrc,
                       uint4* __restrict__ qh, uint4* __restrict__ ql,
                       uint4* __restrict__ kh, uint4* __restrict__ klo,
                       float* __restrict__ ax, float* __restrict__ bx){
    int bs = blockIdx.x, h = blockIdx.y, t = threadIdx.x;
    float qv = qsrc[(size_t)bs*Dm + h*DHd + t];
    float kv = ksrc[(size_t)bs*Dm + h*DHd + t];
    float n2q = blockSum(qv*qv);
    float n2k = blockSum(kv*kv);
    float Kh = headK[h]; float sK = sqrtf(-Kh);
    float aq = sK*sqrtf(n2q);
    float sincq = (aq<1e-6f)?(1.f+aq*aq*(1.f/6.f)):(sinhf(aq)/fmaxf(aq,1e-12f));
    float x0q = sqrtf(-1.f/Kh + sincq*sincq*n2q);
    float ak = sK*sqrtf(n2k);
    float sinck = (ak<1e-6f)?(1.f+ak*ak*(1.f/6.f)):(sinhf(ak)/fmaxf(ak,1e-12f));
    float x0k = sqrtf(-1.f/Kh + sinck*sinck*n2k);
    const float gsc = 0.1767766952966369f;    // 2/sqrt(128)
    __shared__ float sq[128], sk[128];
    sq[t] = gsc*sincq*qv;
    sk[t] = sinck*kv;
    int b = bs >> 11, s = bs & 2047;
    size_t R = ((size_t)(b*Hh + h)<<11) + s;
    if (t==0){ ax[R] = -gsc*x0q; bx[R] = x0k; }
    __syncthreads();
    uint32_t tr = (uint32_t)(R>>7), rl = (uint32_t)(R&127);
    int which = t>>4, g = t&15;
    if (which < 4){
        int kc = g>>3, gg = g&7;
        size_t blk = (((size_t)tr*2 + kc)<<10) + (SWZ(rl*128 + gg*16)>>4);
        const float* sv = (which<2) ? sq : sk;
        Pack8 p;
        #pragma unroll
        for (int j=0;j<8;j++){
            float xv = sv[g*8+j];
            __nv_bfloat16 hh = __float2bfloat16(xv);
            p.b[j] = (which&1) ? __float2bfloat16(xv - __bfloat162float(hh)) : hh;
        }
        uint4* dst = (which==0)?qh:(which==1)?ql:(which==2)?kh:klo;
        dst[blk] = p.v;
    }
}

// causal softmax fused with bf16 hi/lo split.
// Writes ph/pl through the end of the 256-row TILE PAIR so the 256-row PV GEMM
// never reads unwritten blocks; masked entries are exact zeros.
__global__ void k_softmax(const float* __restrict__ probs,
                          uint4* __restrict__ ph, uint4* __restrict__ pl){
    int row = blockIdx.x;
    int qi = row & 2047;
    const float* p = probs + (size_t)row*Sq;
    int t = threadIdx.x;
    int qt = qi >> 7;
    int lastg = ((qt|1)+1) << 4;      // granules through end of 256-pair
    bool act = t < lastg;
    float vals[8];
    float m = -1e30f;
    if (act){
        float4 A = *(const float4*)(p + t*8), B = *(const float4*)(p + t*8 + 4);
        vals[0]=A.x; vals[1]=A.y; vals[2]=A.z; vals[3]=A.w;
        vals[4]=B.x; vals[5]=B.y; vals[6]=B.z; vals[7]=B.w;
        #pragma unroll
        for (int j=0;j<8;j++){
            if (t*8+j > qi) vals[j] = -1e30f;
            m = fmaxf(m, vals[j]);
        }
    } else {
        #pragma unroll
        for (int j=0;j<8;j++) vals[j] = -1e30f;
    }
    m = blockMax(m);
    float s = 0.f;
    #pragma unroll
    for (int j=0;j<8;j++){
        float e = (vals[j] > -1e29f) ? expf(vals[j]-m) : 0.f;
        vals[j] = e; s += e;
    }
    s = blockSum(s);
    float inv = 1.f/s;
    if (act){
        float ps[8];
        #pragma unroll
        for (int j=0;j<8;j++) ps[j] = vals[j]*inv;
        Pack8 H, L; split_pack(ps, H, L);
        uint32_t tr = (uint32_t)row>>7, rl = (uint32_t)row&127;
        int kc = t>>3, gg = t&7;
        size_t blk = (((size_t)tr*(Sq/64) + kc)<<10) + (SWZ(rl*128 + gg*16)>>4);
        ph[blk] = H.v; pl[blk] = L.v;
    }
}

__global__ void k_expmap(const float* __restrict__ u, float* __restrict__ out){
    int row = blockIdx.x, tid = threadIdx.x;
    const float* ur = u + (size_t)row*Dm;
    float loc[8]; float s = 0.f;
    #pragma unroll
    for (int j=0;j<8;j++){ float t = ur[tid + j*256]; loc[j]=t; s += t*t; }
    float n2 = blockSum(s);
    float a = sqrtf(n2);
    float sinc = (a < 1e-6f) ? (1.f + a*a*(1.f/6.f)) : (sinhf(a)/fmaxf(a,1e-12f));
    float x0 = sqrtf(1.f + sinc*sinc*n2);
    float* o = out + (size_t)row*(Dm+1);
    if (tid==0) o[0] = x0;
    #pragma unroll
    for (int j=0;j<8;j++){ int d = tid + j*256; o[1+d] = sinc*loc[j]; }
}

// ================= weight / V-transpose split =================
__global__ void k_split_wT(const float* __restrict__ W, uint4* __restrict__ Hi,
                           uint4* __restrict__ Lo, int K, int N, int ld,
                           int hmode, long long outzG){
    __shared__ float s[64][129];
    int tr = blockIdx.x, kc = blockIdx.y, bz = blockIdx.z;
    int ntc = K >> 6;
    const float* Wb = W + (hmode ? ((long long)(bz>>4)*(long long)Sq*Dm + (long long)(bz&15)*DHd) : 0);
    Hi += (size_t)bz*outzG; Lo += (size_t)bz*outzG;
    int n0 = tr*128, k0 = kc*64;
    int col = threadIdx.x & 127, r0 = threadIdx.x >> 7;
    #pragma unroll
    for (int i=0;i<32;i++){
        int r = r0 + i*2;
        s[r][col] = Wb[(size_t)(k0+r)*ld + n0 + col];
    }
    __syncthreads();
    size_t blk = ((size_t)tr*ntc + kc)*1024;
    #pragma unroll
    for (int i=0;i<4;i++){
        int gid = threadIdx.x + i*256;
        int nl = gid >> 3, g = gid & 7;
        Pack8 uh, ul;
        #pragma unroll
        for (int j=0;j<8;j++){
            float x = s[g*8+j][nl];
            __nv_bfloat16 h = __float2bfloat16(x);
            uh.b[j] = h;
            ul.b[j] = __float2bfloat16(x - __bfloat162float(h));
        }
        uint32_t off = SWZ((uint32_t)(nl*128 + g*16)) >> 4;
        Hi[blk + off] = uh.v;
        Lo[blk + off] = ul.v;
    }
}

// ================= HMMA bf16x3 pipelined GEMM: 256(M) x 128(N) tile, 512 thr =================
// Stage (96KB): [Ah0 | Ah1 | Al0 | Al1 | Bh | Bl] x 16KB. 2-stage ring, mbarrier pipeline.
// MMA triple is PASS-MAJOR within each mt so dependent MMAs on the same accumulator
// are 4 issues apart (covers HMMA latency); per-acc arithmetic order unchanged (hh,hl,lh).
// EPI: 0 fp32 out; 2 fp32 += ADD; 3 TS hi/lo out; 4 gelu + TS hi/lo out; 5 fp32 + rank-1.
// CSKIP: causal pair skip (tnx > 2*tmy+1). KLIM: causal k-chunk limit 4*(tmy+1).
#define STAGE_B 98304
#define HM_SMEM (2*STAGE_B + 1024)

template<int EPI, int CSKIP, int KLIM>
__global__ void __launch_bounds__(512, 1)
hmma_gemm(const uint4* __restrict__ Ah, const uint4* __restrict__ Al,
          const uint4* __restrict__ Bh, const uint4* __restrict__ Bl,
          float* __restrict__ C, const float* __restrict__ ADD,
          uint4* __restrict__ OHi, uint4* __restrict__ OLo,
          const float* __restrict__ AX, const float* __restrict__ BX,
          int nk, int ldc, int ntc, int mtb, int ntb, long long sC, int cmode){
    extern __shared__ char dsm[];
    __shared__ __align__(8) unsigned long long s_mbar[4];   // full0, full1, emp0, emp1
    int tnx = blockIdx.x, tmy = blockIdx.y, bz = blockIdx.z;
    if (CSKIP && tnx > 2*tmy+1) return;
    int nkc = nk;
    if (KLIM) nkc = min(nk, 4*(tmy+1));
    int atr0 = bz*mtb + 2*tmy;          // two A tile-rows: atr0, atr0+1
    int btr  = bz*ntb + tnx;

    uint32_t ab = (smem_u32(dsm) + 1023) & ~1023u;
    int tid = threadIdx.x, wid = tid >> 5, l = tid & 31;
    int wm = wid >> 2, wn = wid & 3;    // 4 x 4 warp grid; warp = 64 rows x 32 cols

    uint32_t mb[2], me[2];
    if (tid == 0){
        MB_INIT(smem_u32(&s_mbar[0]), 1);
        MB_INIT(smem_u32(&s_mbar[1]), 1);
        MB_INIT(smem_u32(&s_mbar[2]), 16);
        MB_INIT(smem_u32(&s_mbar[3]), 16);
    }
    mb[0] = smem_u32(&s_mbar[0]); mb[1] = smem_u32(&s_mbar[1]);
    me[0] = smem_u32(&s_mbar[2]); me[1] = smem_u32(&s_mbar[3]);
    __syncthreads();

    if (tid == 0){
        int pre = min(2, nkc);
        for (int c = 0; c < pre; c++){
            uint32_t base = ab + c*STAGE_B;
            MB_EXPECT_TX(mb[c], STAGE_B);
            BULK16K(base,         (const void*)(Ah + ((size_t)atr0*nk + c)*1024), mb[c]);
            BULK16K(base + 16384, (const void*)(Ah + ((size_t)(atr0+1)*nk + c)*1024), mb[c]);
            BULK16K(base + 32768, (const void*)(Al + ((size_t)atr0*nk + c)*1024), mb[c]);
            BULK16K(base + 49152, (const void*)(Al + ((size_t)(atr0+1)*nk + c)*1024), mb[c]);
            BULK16K(base + 65536, (const void*)(Bh + ((size_t)btr*nk + c)*1024), mb[c]);
            BULK16K(base + 81920, (const void*)(Bl + ((size_t)btr*nk + c)*1024), mb[c]);
        }
    }

    // per-lane ldmatrix row offsets (bytes within a 16KB block)
    int arow[4], brow[2];
    #pragma unroll
    for (int mt=0; mt<4; mt++)
        arow[mt] = ((wm&1)*64 + mt*16 + (l&7) + ((l>>3)&1)*8) * 128;
    #pragma unroll
    for (int p=0; p<2; p++)
        brow[p] = (wn*32 + p*16 + ((l>>4)&1)*8 + (l&7)) * 128;
    int akg = (l>>4)&1, bkg = (l>>3)&1, l7 = l&7;
    uint32_t ablk = (uint32_t)(wm>>1)*16384u;

    float acc[4][4][4];
    #pragma unroll
    for (int i=0;i<4;i++)
        #pragma unroll
        for (int j=0;j<4;j++)
            #pragma unroll
            for (int t=0;t<4;t++) acc[i][j][t] = 0.f;

    for (int c = 0; c < nkc; c++){
        int s = c & 1;
        int ph = (c>>1)&1;
        MB_WAIT(mb[s], ph);
        uint32_t stg = ab + s*STAGE_B;
        uint32_t aHb = stg + ablk;              // Ah block for this warp
        uint32_t aLb = aHb + 32768;             // Al block
        uint32_t bHb = stg + 65536, bLb = stg + 81920;
        #pragma unroll
        for (int kk = 0; kk < 4; kk++){
            int kxA = ((kk*2 + akg) ^ l7) << 4;
            int kxB = ((kk*2 + bkg) ^ l7) << 4;
            uint32_t bhr[4][2], blr[4][2];
            #pragma unroll
            for (int p=0; p<2; p++){
                LDSM4(bhr[2*p][0],bhr[2*p][1],bhr[2*p+1][0],bhr[2*p+1][1], bHb + brow[p] + kxB);
                LDSM4(blr[2*p][0],blr[2*p][1],blr[2*p+1][0],blr[2*p+1][1], bLb + brow[p] + kxB);
            }
            #pragma unroll
            for (int mt=0; mt<4; mt++){
                uint32_t ahf[4], alf[4];
                LDSM4(ahf[0],ahf[1],ahf[2],ahf[3], aHb + arow[mt] + kxA);
                LDSM4(alf[0],alf[1],alf[2],alf[3], aLb + arow[mt] + kxA);
                // pass-major: dependent MMAs on the same acc are 4 issues apart
                #pragma unroll
                for (int nt=0; nt<4; nt++)
                    MMA16816(acc[mt][nt], ahf, bhr[nt][0], bhr[nt][1]);
                #pragma unroll
                for (int nt=0; nt<4; nt++)
                    MMA16816(acc[mt][nt], ahf, blr[nt][0], blr[nt][1]);
                #pragma unroll
                for (int nt=0; nt<4; nt++)
                    MMA16816(acc[mt][nt], alf, bhr[nt][0], bhr[nt][1]);
            }
        }
        // this warp is done reading stage s
        if (l == 0) MB_ARRIVE(me[s]);
        // producer: wait all 16 warps done with stage s, then refill it for chunk c+2
        if (tid == 0 && c + 2 < nkc){
            MB_WAIT(me[s], ph);
            int cc = c + 2;
            uint32_t base = ab + s*STAGE_B;
            MB_EXPECT_TX(mb[s], STAGE_B);
            BULK16K(base,         (const void*)(Ah + ((size_t)atr0*nk + cc)*1024), mb[s]);
            BULK16K(base + 16384, (const void*)(Ah + ((size_t)(atr0+1)*nk + cc)*1024), mb[s]);
            BULK16K(base + 32768, (const void*)(Al + ((size_t)atr0*nk + cc)*1024), mb[s]);
            BULK16K(base + 49152, (const void*)(Al + ((size_t)(atr0+1)*nk + cc)*1024), mb[s]);
            BULK16K(base + 65536, (const void*)(Bh + ((size_t)btr*nk + cc)*1024), mb[s]);
            BULK16K(base + 81920, (const void*)(Bl + ((size_t)btr*nk + cc)*1024), mb[s]);
        }
    }

    // -------- epilogue --------
    if (EPI == 3 || EPI == 4){
        int otrBase, ocol0;
        if (cmode){ otrBase = (bz>>4)*(Sq/128) + tmy*2; ocol0 = (bz&15)*DHd + tnx*128; }
        else      { otrBase = tmy*2;                    ocol0 = tnx*128; }
        int otr = otrBase + (wm>>1);
        char* HiB = (char*)OHi;
        char* LoB = (char*)OLo;
        #pragma unroll
        for (int mt=0; mt<4; mt++){
            int rl = (wm&1)*64 + mt*16 + (l>>2);     // row within 128-tile
            uint32_t ro0 = (uint32_t)(rl*128), ro1 = (uint32_t)((rl+8)*128);
            #pragma unroll
            for (int nt=0; nt<4; nt++){
                int col = ocol0 + wn*32 + nt*8 + (l&3)*2;
                float v0 = acc[mt][nt][0], v1 = acc[mt][nt][1];
                float v2 = acc[mt][nt][2], v3 = acc[mt][nt][3];
                if (EPI == 4){
                    v0 = 0.5f*v0*(1.f + erff(v0*0.7071067811865475f));
                    v1 = 0.5f*v1*(1.f + erff(v1*0.7071067811865475f));
                    v2 = 0.5f*v2*(1.f + erff(v2*0.7071067811865475f));
                    v3 = 0.5f*v3*(1.f + erff(v3*0.7071067811865475f));
                }
                int kcn = col>>6, g = (col>>3)&7, w2 = (col&7)*2;
                size_t blkB = (((size_t)otr*ntc + kcn)<<14);
                uint32_t o0 = SWZ(ro0 + g*16) + w2;
                uint32_t o1 = SWZ(ro1 + g*16) + w2;
                __nv_bfloat16 h0 = __float2bfloat16(v0), h1 = __float2bfloat16(v1);
                __nv_bfloat16 h2 = __float2bfloat16(v2), h3 = __float2bfloat16(v3);
                __nv_bfloat16 l0 = __float2bfloat16(v0 - __bfloat162float(h0));
                __nv_bfloat16 l1 = __float2bfloat16(v1 - __bfloat162float(h1));
                __nv_bfloat16 l2 = __float2bfloat16(v2 - __bfloat162float(h2));
                __nv_bfloat16 l3 = __float2bfloat16(v3 - __bfloat162float(h3));
                *(uint32_t*)(HiB + blkB + o0) = (uint32_t)__bfloat16_as_ushort(h0) | ((uint32_t)__bfloat16_as_ushort(h1)<<16);
                *(uint32_t*)(LoB + blkB + o0) = (uint32_t)__bfloat16_as_ushort(l0) | ((uint32_t)__bfloat16_as_ushort(l1)<<16);
                *(uint32_t*)(HiB + blkB + o1) = (uint32_t)__bfloat16_as_ushort(h2) | ((uint32_t)__bfloat16_as_ushort(h3)<<16);
                *(uint32_t*)(LoB + blkB + o1) = (uint32_t)__bfloat16_as_ushort(l2) | ((uint32_t)__bfloat16_as_ushort(l3)<<16);
            }
        }
    } else {
        long long offC = cmode ? ((long long)(bz>>4)*(long long)Sq*Dm + (long long)(bz&15)*DHd)
                               : (long long)bz*sC;
        float* Cb = C + offC + (size_t)tmy*256*ldc + (size_t)tnx*128;
        const float* Ab = (EPI==2) ? (ADD + offC + (size_t)tmy*256*ldc + (size_t)tnx*128) : nullptr;
        const float* axp = (EPI==5) ? (AX + (size_t)bz*Sq + tmy*256) : nullptr;
        const float* bxp = (EPI==5) ? (BX + (size_t)bz*Sq + tnx*128) : nullptr;
        #pragma unroll
        for (int mt=0; mt<4; mt++){
            int r0 = wm*64 + mt*16 + (l>>2);
            float a0 = 0.f, a1 = 0.f;
            if (EPI==5){ a0 = axp[r0]; a1 = axp[r0+8]; }
            #pragma unroll
            for (int nt=0; nt<4; nt++){
                int cc = wn*32 + nt*8 + (l&3)*2;
                float v0 = acc[mt][nt][0], v1 = acc[mt][nt][1];
                float v2 = acc[mt][nt][2], v3 = acc[mt][nt][3];
                if (EPI==5){
                    float b0 = bxp[cc], b1 = bxp[cc+1];
                    v0 += a0*b0; v1 += a0*b1; v2 += a1*b0; v3 += a1*b1;
                }
                if (EPI==2){
                    float2 x0 = *(const float2*)&Ab[(size_t)r0*ldc + cc];
                    float2 x1 = *(const float2*)&Ab[(size_t)(r0+8)*ldc + cc];
                    v0 += x0.x; v1 += x0.y; v2 += x1.x; v3 += x1.y;
                }
                *(float2*)&Cb[(size_t)r0*ldc + cc]     = make_float2(v0, v1);
                *(float2*)&Cb[(size_t)(r0+8)*ldc + cc] = make_float2(v2, v3);
            }
        }
    }
}

// ================= launch =================
extern "C" void kernel_launch(void* const* d_in, const int* in_sizes, int n_in,
                              void* d_out, int out_size){
    const float* x      = (const float*)d_in[0];
    const float* scale1 = (const float*)d_in[2];
    const float* scale2 = (const float*)d_in[3];
    const float* Wq     = (const float*)d_in[4];
    const float* Wk     = (const float*)d_in[5];
    const float* Wv     = (const float*)d_in[6];
    const float* Wo     = (const float*)d_in[7];
    const float* headK  = (const float*)d_in[8];
    const float* W1     = (const float*)d_in[9];
    const float* W2     = (const float*)d_in[10];
    float* out = (float*)d_out;

    float *u,*q,*k,*vv,*probs,*ax,*bx;
    cudaGetSymbolAddress((void**)&u,    g_u);
    cudaGetSymbolAddress((void**)&q,    g_q);
    cudaGetSymbolAddress((void**)&k,    g_k);
    cudaGetSymbolAddress((void**)&vv,   g_vv);
    cudaGetSymbolAddress((void**)&probs,g_probs);
    cudaGetSymbolAddress((void**)&ax,   g_ax);
    cudaGetSymbolAddress((void**)&bx,   g_bx);

    uint4 *vh,*vl,*ath,*atl,*fh,*fl,*qh,*ql_,*kh,*klo,*ph,*pl,*vth,*vtl;
    uint4 *wqh,*wql,*wkh,*wkl,*wvh,*wvl,*woh,*wol,*w1h,*w1l,*w2h,*w2l;
    cudaGetSymbolAddress((void**)&vh,  g_vh);   cudaGetSymbolAddress((void**)&vl,  g_vl);
    cudaGetSymbolAddress((void**)&ath, g_ath);  cudaGetSymbolAddress((void**)&atl, g_atl);
    cudaGetSymbolAddress((void**)&fh,  g_fh);   cudaGetSymbolAddress((void**)&fl,  g_fl);
    cudaGetSymbolAddress((void**)&qh,  g_qh);   cudaGetSymbolAddress((void**)&ql_, g_ql);
    cudaGetSymbolAddress((void**)&kh,  g_kh);   cudaGetSymbolAddress((void**)&klo, g_klo);
    cudaGetSymbolAddress((void**)&ph,  g_ph);   cudaGetSymbolAddress((void**)&pl,  g_pl);
    cudaGetSymbolAddress((void**)&vth, g_vth);  cudaGetSymbolAddress((void**)&vtl, g_vtl);
    cudaGetSymbolAddress((void**)&wqh, g_WqTh); cudaGetSymbolAddress((void**)&wql, g_WqTl);
    cudaGetSymbolAddress((void**)&wkh, g_WkTh); cudaGetSymbolAddress((void**)&wkl, g_WkTl);
    cudaGetSymbolAddress((void**)&wvh, g_WvTh); cudaGetSymbolAddress((void**)&wvl, g_WvTl);
    cudaGetSymbolAddress((void**)&woh, g_WoTh); cudaGetSymbolAddress((void**)&wol, g_WoTl);
    cudaGetSymbolAddress((void**)&w1h, g_W1Th); cudaGetSymbolAddress((void**)&w1l, g_W1Tl);
    cudaGetSymbolAddress((void**)&w2h, g_W2Th); cudaGetSymbolAddress((void**)&w2l, g_W2Tl);

    cudaFuncSetAttribute(hmma_gemm<0,0,0>, cudaFuncAttributeMaxDynamicSharedMemorySize, HM_SMEM);
    cudaFuncSetAttribute(hmma_gemm<2,0,0>, cudaFuncAttributeMaxDynamicSharedMemorySize, HM_SMEM);
    cudaFuncSetAttribute(hmma_gemm<5,1,0>, cudaFuncAttributeMaxDynamicSharedMemorySize, HM_SMEM);
    cudaFuncSetAttribute(hmma_gemm<3,0,1>, cudaFuncAttributeMaxDynamicSharedMemorySize, HM_SMEM);
    cudaFuncSetAttribute(hmma_gemm<4,0,0>, cudaFuncAttributeMaxDynamicSharedMemorySize, HM_SMEM);

    // 0) weight splits (transposed to [N,K] TS)
    k_split_wT<<<dim3(Dm/128,  Dm/64,  1),256>>>(Wq, wqh, wql, Dm, Dm, Dm, 0, 0);
    k_split_wT<<<dim3(Dm/128,  Dm/64,  1),256>>>(Wk, wkh, wkl, Dm, Dm, Dm, 0, 0);
    k_split_wT<<<dim3(Dm/128,  Dm/64,  1),256>>>(Wv, wvh, wvl, Dm, Dm, Dm, 0, 0);
    k_split_wT<<<dim3(Dm/128,  Dm/64,  1),256>>>(Wo, woh, wol, Dm, Dm, Dm, 0, 0);
    k_split_wT<<<dim3(DFFd/128,Dm/64,  1),256>>>(W1, w1h, w1l, Dm, DFFd, DFFd, 0, 0);
    k_split_wT<<<dim3(Dm/128,  DFFd/64,1),256>>>(W2, w2h, w2l, DFFd, Dm, Dm, 0, 0);

    // 1) u0 = log(x); v1 = norm1(u0) -> u fp32 + vh/vl TS
    k_lognorm1<<<ROWS,256>>>(x, scale1, u, vh, vl);

    // 2) QKV projections (M-tiles of 256)
    dim3 gQ(Dm/128, ROWS/256);
    hmma_gemm<0,0,0><<<gQ,512,HM_SMEM>>>(vh, vl, wqh, wql, q,  nullptr, 0,0, 0,0, Dm/64, Dm, 0, ROWS/128, Dm/128, 0, 0);
    hmma_gemm<0,0,0><<<gQ,512,HM_SMEM>>>(vh, vl, wkh, wkl, k,  nullptr, 0,0, 0,0, Dm/64, Dm, 0, ROWS/128, Dm/128, 0, 0);
    hmma_gemm<0,0,0><<<gQ,512,HM_SMEM>>>(vh, vl, wvh, wvl, vv, nullptr, 0,0, 0,0, Dm/64, Dm, 0, ROWS/128, Dm/128, 0, 0);

    // 3) lorentz lift -> TS hi/lo (128 dims) + rank-1 vectors
    k_qlkl<<<dim3(ROWS,Hh),128>>>(headK, q, k, qh, ql_, kh, klo, ax, bx);

    // 4) causal scores: probs = q@k^T + ax⊗bx (pair-tile causal skip)
    hmma_gemm<5,1,0><<<dim3(Sq/128, Sq/256, BHn),512,HM_SMEM>>>(
        qh, ql_, kh, klo, probs, nullptr, 0,0, ax, bx, 2, Sq, 0, Sq/128, Sq/128, (long long)Sq*Sq, 0);

    // 5) causal softmax fused with bf16 split -> ph/pl TS (pair-boundary zero fill)
    k_softmax<<<BHn*Sq,256>>>(probs, ph, pl);

    // 6) V^T per-head split, then PV (k-limited) -> ath/atl TS directly
    k_split_wT<<<dim3(1, Sq/64, BHn),256>>>(vv, vth, vtl, Sq, DHd, Dm, 1, (long long)(Sq/64)*1024);
    hmma_gemm<3,0,1><<<dim3(1, Sq/256, BHn),512,HM_SMEM>>>(
        ph, pl, vth, vtl, nullptr, nullptr, ath, atl, 0,0, Sq/64, 0, Dm/64, Sq/128, 1, 0, 1);

    // 7) Wo projection + residual: u += attn@Wo
    hmma_gemm<2,0,0><<<gQ,512,HM_SMEM>>>(ath, atl, woh, wol, u, u, 0,0, 0,0, Dm/64, Dm, 0, ROWS/128, Dm/128, 0, 0);

    // 8) v2 = norm2(u1) -> vh/vl TS
    k_norm2<<<ROWS,256>>>(u, scale2, vh, vl);

    // 9) FFN up + exact gelu -> fh/fl TS directly
    hmma_gemm<4,0,0><<<dim3(DFFd/128, ROWS/256),512,HM_SMEM>>>(
        vh, vl, w1h, w1l, nullptr, nullptr, fh, fl, 0,0, Dm/64, 0, DFFd/64, ROWS/128, DFFd/128, 0, 0);

    // 10) FFN down + residual: u += gelu@W2
    hmma_gemm<2,0,0><<<gQ,512,HM_SMEM>>>(fh, fl, w2h, w2l, u, u, 0,0, 0,0, DFFd/64, Dm, 0, ROWS/128, Dm/128, 0, 0);

    // 11) out = exp_map(u2)
    k_expmap<<<ROWS,256>>>(u, out);
}